// round 1
// baseline (speedup 1.0000x reference)
#include <cuda_runtime.h>
#include <cuda_bf16.h>
#include <math.h>

// ---------------------------------------------------------------------------
// Problem constants
// ---------------------------------------------------------------------------
#define BATCH   4096
#define LSTM    400
#define VOCAB   73
#define NATTN   10
#define CHARLEN 64
#define NGATE   1600            // 4*LSTM
#define K1      476             // w_prev(73)+inputs(3)+h(400)
#define K1PAD   480
#define K23     876             // inputs(3)+h(400)+w(73)+hrec(400)
#define K23PAD  880
#define ATTN_IN 476

// ---------------------------------------------------------------------------
// Scratch (device globals -- no allocation allowed)
// ---------------------------------------------------------------------------
__device__ float g_Wt1[K1PAD  * NGATE];
__device__ float g_Wt2[K23PAD * NGATE];
__device__ float g_Wt3[K23PAD * NGATE];
__device__ float g_X   [BATCH * K23PAD];
__device__ float g_gates[BATCH * NGATE];
__device__ float g_h1n [BATCH * LSTM];
__device__ float g_h2n [BATCH * LSTM];
__device__ float g_w   [BATCH * VOCAB];

// ---------------------------------------------------------------------------
// Weight pack: Wt[k][n] = (k < in_w) ? W_ih[n][k] : W_hh[n][k-in_w]; pad rows 0
// Tiled transpose, coalesced both sides.
// ---------------------------------------------------------------------------
__global__ void pack_w(const float* __restrict__ Wih, const float* __restrict__ Whh,
                       float* __restrict__ Wt, int in_w, int kpad)
{
    __shared__ float tile[32][33];
    int n0 = blockIdx.x * 32, k0 = blockIdx.y * 32;
    int tx = threadIdx.x, ty = threadIdx.y;
    int n = n0 + ty;          // row of W (gate index), always < 1600
    int k = k0 + tx;          // col of W (input feature)
    float v = 0.f;
    if (k < in_w)                 v = Wih[n * in_w + k];
    else if (k < in_w + LSTM)     v = Whh[n * LSTM + (k - in_w)];
    tile[ty][tx] = v;
    __syncthreads();
    int kk = k0 + ty, nn = n0 + tx;
    if (kk < kpad) Wt[kk * NGATE + nn] = tile[tx][ty];
}

// ---------------------------------------------------------------------------
// Input concat packs
// ---------------------------------------------------------------------------
__global__ void pack_x1(const float* __restrict__ w_prev, const float* __restrict__ inputs,
                        const float* __restrict__ h1, float* __restrict__ X)
{
    int idx = blockIdx.x * blockDim.x + threadIdx.x;
    if (idx >= BATCH * K1PAD) return;
    int b = idx / K1PAD, c = idx - b * K1PAD;
    float v;
    if      (c < 73)  v = w_prev[b * 73 + c];
    else if (c < 76)  v = inputs[b * 3 + (c - 73)];
    else if (c < 476) v = h1[b * LSTM + (c - 76)];
    else              v = 0.f;
    X[idx] = v;
}

__global__ void pack_x23(const float* __restrict__ inputs, const float* __restrict__ h,
                         const float* __restrict__ w, const float* __restrict__ hrec,
                         float* __restrict__ X)
{
    int idx = blockIdx.x * blockDim.x + threadIdx.x;
    if (idx >= BATCH * K23PAD) return;
    int b = idx / K23PAD, c = idx - b * K23PAD;
    float v;
    if      (c < 3)   v = inputs[b * 3 + c];
    else if (c < 403) v = h[b * LSTM + (c - 3)];
    else if (c < 476) v = w[b * VOCAB + (c - 403)];
    else if (c < 876) v = hrec[b * LSTM + (c - 476)];
    else              v = 0.f;
    X[idx] = v;
}

// ---------------------------------------------------------------------------
// SGEMM: C[M,N] = A[M,KPAD] * B[KPAD,N] + bias[N], M=4096, N=1600
// 128x128 block tile, 8x8 per thread, BK=8, 256 threads.
// ---------------------------------------------------------------------------
__global__ __launch_bounds__(256, 2)
void sgemm_bias(const float* __restrict__ A, const float* __restrict__ B,
                const float* __restrict__ bias, float* __restrict__ C, int KPAD)
{
    const int N = NGATE;
    __shared__ float As[8][128];
    __shared__ float Bs[8][128];
    int tid = threadIdx.x;
    int bm = blockIdx.y, bn = blockIdx.x;

    int row0 = (tid / 16) * 8;
    int col0 = (tid % 16) * 8;

    int arow = tid >> 1;            // 0..127
    int acol = (tid & 1) * 4;       // 0 or 4
    int brow = tid >> 5;            // 0..7
    int bcol = (tid & 31) * 4;      // 0..124

    const float* Aptr = A + (size_t)(bm * 128 + arow) * KPAD + acol;
    int bcol_g = bn * 128 + bcol;
    const float* Bptr = (bcol_g < N) ? (B + brow * N + bcol_g) : nullptr;

    float acc[8][8];
    #pragma unroll
    for (int i = 0; i < 8; i++)
        #pragma unroll
        for (int j = 0; j < 8; j++) acc[i][j] = 0.f;

    for (int k0 = 0; k0 < KPAD; k0 += 8) {
        float4 av = *reinterpret_cast<const float4*>(Aptr + k0);
        As[acol + 0][arow] = av.x;
        As[acol + 1][arow] = av.y;
        As[acol + 2][arow] = av.z;
        As[acol + 3][arow] = av.w;
        float4 bv = Bptr ? *reinterpret_cast<const float4*>(Bptr + (size_t)k0 * N)
                         : make_float4(0.f, 0.f, 0.f, 0.f);
        *reinterpret_cast<float4*>(&Bs[brow][bcol]) = bv;
        __syncthreads();
        #pragma unroll
        for (int kk = 0; kk < 8; kk++) {
            float a[8], bb[8];
            float4 a0 = *reinterpret_cast<const float4*>(&As[kk][row0]);
            float4 a1 = *reinterpret_cast<const float4*>(&As[kk][row0 + 4]);
            a[0]=a0.x; a[1]=a0.y; a[2]=a0.z; a[3]=a0.w;
            a[4]=a1.x; a[5]=a1.y; a[6]=a1.z; a[7]=a1.w;
            float4 b0 = *reinterpret_cast<const float4*>(&Bs[kk][col0]);
            float4 b1 = *reinterpret_cast<const float4*>(&Bs[kk][col0 + 4]);
            bb[0]=b0.x; bb[1]=b0.y; bb[2]=b0.z; bb[3]=b0.w;
            bb[4]=b1.x; bb[5]=b1.y; bb[6]=b1.z; bb[7]=b1.w;
            #pragma unroll
            for (int i = 0; i < 8; i++)
                #pragma unroll
                for (int j = 0; j < 8; j++)
                    acc[i][j] = fmaf(a[i], bb[j], acc[i][j]);
        }
        __syncthreads();
    }

    int crow0 = bm * 128 + row0;
    int ccol0 = bn * 128 + col0;
    if (ccol0 + 8 <= N) {
        float bsv[8];
        #pragma unroll
        for (int j = 0; j < 8; j++) bsv[j] = bias[ccol0 + j];
        #pragma unroll
        for (int i = 0; i < 8; i++) {
            float* crow = C + (size_t)(crow0 + i) * N + ccol0;
            #pragma unroll
            for (int j = 0; j < 8; j++) crow[j] = acc[i][j] + bsv[j];
        }
    }
}

// ---------------------------------------------------------------------------
// LSTM elementwise: gates [B,1600] in (i,f,g,o) order -> h_out [B,400]
// ---------------------------------------------------------------------------
__device__ __forceinline__ float sigmoidf_(float x) { return 1.f / (1.f + expf(-x)); }

__global__ void lstm_elem(const float* __restrict__ gates, const float* __restrict__ c_in,
                          float* __restrict__ h_out)
{
    int idx = blockIdx.x * blockDim.x + threadIdx.x;
    if (idx >= BATCH * LSTM) return;
    int b = idx / LSTM, j = idx - b * LSTM;
    const float* g = gates + (size_t)b * NGATE;
    float ig = sigmoidf_(g[j]);
    float fg = sigmoidf_(g[400 + j]);
    float gg = tanhf(g[800 + j]);
    float og = sigmoidf_(g[1200 + j]);
    float c = fg * c_in[idx] + ig * gg;
    h_out[idx] = og * tanhf(c);
}

// ---------------------------------------------------------------------------
// Attention: per-batch block. Computes softplus(attn_in @ W_attn^T + b),
// gaussian-mixture phi over char positions, masked einsum with AV -> w [B,73]
// ---------------------------------------------------------------------------
__global__ void attention_kernel(const float* __restrict__ w_prev,
                                 const float* __restrict__ inputs,
                                 const float* __restrict__ h1n,
                                 const float* __restrict__ kappa,
                                 const float* __restrict__ W_attn,
                                 const float* __restrict__ b_attn,
                                 const float* __restrict__ AV,
                                 const int* __restrict__ lens,
                                 float* __restrict__ w_out)
{
    int b = blockIdx.x;
    __shared__ float s_in[ATTN_IN];
    __shared__ float s_par[3 * NATTN];
    __shared__ float s_alpha[NATTN], s_beta[NATTN], s_kap[NATTN];
    __shared__ float s_phi[CHARLEN];
    int t = threadIdx.x; // 128 threads

    for (int i = t; i < 73; i += 128)  s_in[i]      = w_prev[b * 73 + i];
    if (t < 3)                          s_in[73 + t] = inputs[b * 3 + t];
    for (int i = t; i < 400; i += 128) s_in[76 + i] = h1n[b * LSTM + i];
    __syncthreads();

    {
        int out = t >> 2, lane = t & 3;
        float acc = 0.f;
        if (out < 30) {
            const float* wr = W_attn + out * ATTN_IN;
            for (int k = lane; k < ATTN_IN; k += 4) acc = fmaf(s_in[k], wr[k], acc);
        }
        acc += __shfl_down_sync(0xffffffffu, acc, 2);
        acc += __shfl_down_sync(0xffffffffu, acc, 1);
        if (lane == 0 && out < 30) {
            float x = acc + b_attn[out];
            s_par[out] = (x > 20.f) ? x : log1pf(expf(x));
        }
    }
    __syncthreads();

    if (t < NATTN) {
        s_alpha[t] = s_par[t];
        s_beta[t]  = fmaxf(s_par[NATTN + t], 0.01f);
        s_kap[t]   = kappa[b * NATTN + t] + s_par[2 * NATTN + t] * 0.04f; // /25
    }
    __syncthreads();

    int len = lens[b];
    if (t < CHARLEN) {
        float u = (float)t;
        float phi = 0.f;
        #pragma unroll
        for (int i = 0; i < NATTN; i++) {
            float d = s_kap[i] - u;
            phi += s_alpha[i] * expf(-d * d / s_beta[i]);
        }
        s_phi[t] = (t < len) ? phi : 0.f;
    }
    __syncthreads();

    for (int v = t; v < VOCAB; v += 128) {
        float acc = 0.f;
        const float* av = AV + (size_t)b * (CHARLEN * VOCAB) + v;
        #pragma unroll 8
        for (int c = 0; c < CHARLEN; c++) acc = fmaf(s_phi[c], av[c * VOCAB], acc);
        w_out[b * VOCAB + v] = acc;
    }
}

// ---------------------------------------------------------------------------
// Launch
// ---------------------------------------------------------------------------
extern "C" void kernel_launch(void* const* d_in, const int* in_sizes, int n_in,
                              void* d_out, int out_size)
{
    const float* inputs = (const float*)d_in[0];
    const float* h1     = (const float*)d_in[1];
    const float* c1     = (const float*)d_in[2];
    const float* h2     = (const float*)d_in[3];
    const float* c2     = (const float*)d_in[4];
    const float* h3     = (const float*)d_in[5];
    const float* c3     = (const float*)d_in[6];
    const float* kappa  = (const float*)d_in[7];
    const float* w_prev = (const float*)d_in[8];
    const float* AV     = (const float*)d_in[9];
    const int*   lens   = (const int*)  d_in[10];
    const float* W_ih1  = (const float*)d_in[11];
    const float* W_hh1  = (const float*)d_in[12];
    const float* b1     = (const float*)d_in[13];
    const float* W_attn = (const float*)d_in[14];
    const float* b_attn = (const float*)d_in[15];
    const float* W_ih2  = (const float*)d_in[16];
    const float* W_hh2  = (const float*)d_in[17];
    const float* b2     = (const float*)d_in[18];
    const float* W_ih3  = (const float*)d_in[19];
    const float* W_hh3  = (const float*)d_in[20];
    const float* b3     = (const float*)d_in[21];
    float* out = (float*)d_out;

    float *Wt1, *Wt2, *Wt3, *X, *gates, *h1n, *h2n, *wbuf;
    cudaGetSymbolAddress((void**)&Wt1,   g_Wt1);
    cudaGetSymbolAddress((void**)&Wt2,   g_Wt2);
    cudaGetSymbolAddress((void**)&Wt3,   g_Wt3);
    cudaGetSymbolAddress((void**)&X,     g_X);
    cudaGetSymbolAddress((void**)&gates, g_gates);
    cudaGetSymbolAddress((void**)&h1n,   g_h1n);
    cudaGetSymbolAddress((void**)&h2n,   g_h2n);
    cudaGetSymbolAddress((void**)&wbuf,  g_w);

    dim3 tb(32, 32);
    pack_w<<<dim3(NGATE / 32, (K1PAD  + 31) / 32), tb>>>(W_ih1, W_hh1, Wt1, 76,  K1PAD);
    pack_w<<<dim3(NGATE / 32, (K23PAD + 31) / 32), tb>>>(W_ih2, W_hh2, Wt2, 476, K23PAD);
    pack_w<<<dim3(NGATE / 32, (K23PAD + 31) / 32), tb>>>(W_ih3, W_hh3, Wt3, 476, K23PAD);

    dim3 ggrid((NGATE + 127) / 128, BATCH / 128); // (13, 32)
    int nElem = BATCH * LSTM;

    // LSTM 1
    pack_x1<<<(BATCH * K1PAD + 255) / 256, 256>>>(w_prev, inputs, h1, X);
    sgemm_bias<<<ggrid, 256>>>(X, Wt1, b1, gates, K1PAD);
    lstm_elem<<<(nElem + 255) / 256, 256>>>(gates, c1, h1n);

    // Attention
    attention_kernel<<<BATCH, 128>>>(w_prev, inputs, h1n, kappa, W_attn, b_attn,
                                     AV, lens, wbuf);

    // LSTM 2
    pack_x23<<<(BATCH * K23PAD + 255) / 256, 256>>>(inputs, h1n, wbuf, h2, X);
    sgemm_bias<<<ggrid, 256>>>(X, Wt2, b2, gates, K23PAD);
    lstm_elem<<<(nElem + 255) / 256, 256>>>(gates, c2, h2n);

    // LSTM 3
    pack_x23<<<(BATCH * K23PAD + 255) / 256, 256>>>(inputs, h2n, wbuf, h3, X);
    sgemm_bias<<<ggrid, 256>>>(X, Wt3, b3, gates, K23PAD);
    lstm_elem<<<(nElem + 255) / 256, 256>>>(gates, c3, out);
}

// round 3
// speedup vs baseline: 1.9421x; 1.9421x over previous
#include <cuda_runtime.h>
#include <cuda_bf16.h>
#include <math.h>
#include <stdint.h>

// ---------------------------------------------------------------------------
// Problem constants
// ---------------------------------------------------------------------------
#define BATCH   4096
#define LSTM    400
#define VOCAB   73
#define NATTN   10
#define CHARLEN 64
#define NGATE   1600
#define K1PAD   480
#define K23PAD  896
#define ATTN_IN 476
#define NTILE   160

// ---------------------------------------------------------------------------
// Scratch (device globals)
// ---------------------------------------------------------------------------
// X stored K-MAJOR: X[k][m], leading dim 4096. Weights K-major: Wt[k][np], ld 1600,
// np = unit*4+gate (gate-interleaved).
__device__ float g_Wt1[K23PAD * NGATE];
__device__ float g_Wt2[K23PAD * NGATE];
__device__ float g_Wt3[K23PAD * NGATE];
__device__ float g_X  [K23PAD * BATCH];
__device__ float g_h1n[BATCH * LSTM];
__device__ float g_h2n[BATCH * LSTM];
__device__ float g_w  [BATCH * VOCAB];

__device__ __forceinline__ float to_tf32(float x) {
    float r; asm("cvt.rna.tf32.f32 %0, %1;" : "=f"(r) : "f"(x)); return r;
}

#define CPASYNC16(dst, src) \
    asm volatile("cp.async.cg.shared.global [%0], [%1], 16;" :: "r"(dst), "l"(src) : "memory")

__device__ __forceinline__ uint32_t smem_to_u32(const void* p) {
    uint32_t a;
    asm("{ .reg .u64 t; cvta.to.shared.u64 t, %1; cvt.u32.u64 %0, t; }" : "=r"(a) : "l"(p));
    return a;
}

__device__ __forceinline__ void mma_tf32(float* d, const uint32_t* a, const uint32_t* b) {
    asm volatile(
        "mma.sync.aligned.m16n8k8.row.col.f32.tf32.tf32.f32 "
        "{%0,%1,%2,%3}, {%4,%5,%6,%7}, {%8,%9}, {%0,%1,%2,%3};"
        : "+f"(d[0]), "+f"(d[1]), "+f"(d[2]), "+f"(d[3])
        : "r"(a[0]), "r"(a[1]), "r"(a[2]), "r"(a[3]), "r"(b[0]), "r"(b[1]));
}

// ---------------------------------------------------------------------------
// Tiled-transpose packs (coalesced read + coalesced write)
// block (32,8); each block does a 32x32 tile.
// ---------------------------------------------------------------------------
// Weights: Wt[k][np], np=unit*4+gate -> original row n=gate*400+unit
__global__ void pack_w_t(const float* __restrict__ Wih, const float* __restrict__ Whh,
                         float* __restrict__ Wt, int in_w, int kpad)
{
    __shared__ float tile[32][33];
    int k0 = blockIdx.x * 32, n0 = blockIdx.y * 32;
    int tx = threadIdx.x, ty = threadIdx.y;
    #pragma unroll
    for (int i = 0; i < 4; i++) {
        int np = n0 + ty + i * 8;
        int n = (np & 3) * LSTM + (np >> 2);
        int k = k0 + tx;
        float v = 0.f;
        if (k < in_w)             v = Wih[n * in_w + k];
        else if (k < in_w + LSTM) v = Whh[n * LSTM + (k - in_w)];
        tile[ty + i * 8][tx] = to_tf32(v);
    }
    __syncthreads();
    #pragma unroll
    for (int i = 0; i < 4; i++) {
        int k = k0 + ty + i * 8;
        Wt[(size_t)k * NGATE + n0 + tx] = tile[tx][ty + i * 8];
    }
}

__global__ void pack_x1_t(const float* __restrict__ w_prev, const float* __restrict__ inputs,
                          const float* __restrict__ h1, float* __restrict__ X)
{
    __shared__ float tile[32][33];
    int k0 = blockIdx.x * 32, m0 = blockIdx.y * 32;
    int tx = threadIdx.x, ty = threadIdx.y;
    #pragma unroll
    for (int i = 0; i < 4; i++) {
        int m = m0 + ty + i * 8, k = k0 + tx;
        float v = 0.f;
        if      (k < 73)  v = w_prev[m * 73 + k];
        else if (k < 76)  v = inputs[m * 3 + (k - 73)];
        else if (k < 476) v = h1[m * LSTM + (k - 76)];
        tile[ty + i * 8][tx] = to_tf32(v);
    }
    __syncthreads();
    #pragma unroll
    for (int i = 0; i < 4; i++) {
        int k = k0 + ty + i * 8;
        X[(size_t)k * BATCH + m0 + tx] = tile[tx][ty + i * 8];
    }
}

__global__ void pack_x23_t(const float* __restrict__ inputs, const float* __restrict__ h,
                           const float* __restrict__ w, const float* __restrict__ hrec,
                           float* __restrict__ X)
{
    __shared__ float tile[32][33];
    int k0 = blockIdx.x * 32, m0 = blockIdx.y * 32;
    int tx = threadIdx.x, ty = threadIdx.y;
    #pragma unroll
    for (int i = 0; i < 4; i++) {
        int m = m0 + ty + i * 8, k = k0 + tx;
        float v = 0.f;
        if      (k < 3)   v = inputs[m * 3 + k];
        else if (k < 403) v = h[m * LSTM + (k - 3)];
        else if (k < 476) v = w[m * VOCAB + (k - 403)];
        else if (k < 876) v = hrec[m * LSTM + (k - 476)];
        tile[ty + i * 8][tx] = to_tf32(v);
    }
    __syncthreads();
    #pragma unroll
    for (int i = 0; i < 4; i++) {
        int k = k0 + ty + i * 8;
        X[(size_t)k * BATCH + m0 + tx] = tile[tx][ty + i * 8];
    }
}

// ---------------------------------------------------------------------------
// Fused tf32 mma.sync GEMM + LSTM epilogue.
// CTA tile 128(M) x 160(N), BK=32, 8 warps (4M x 2N), warp tile 32x80.
// A smem: k-major [32][132] floats; B smem: [32][164] floats (conflict-free LDS).
// ---------------------------------------------------------------------------
#define A_STRIDE 132
#define B_STRIDE 164
#define A_BYTES  (32 * A_STRIDE * 4)     // 16896
#define B_BYTES  (32 * B_STRIDE * 4)     // 20992
#define STAGE_BYTES (A_BYTES + B_BYTES)  // 37888
#define SMEM_GEMM (2 * STAGE_BYTES)      // 75776

__global__ __launch_bounds__(256, 1)
void gemm_lstm(const float* __restrict__ A, const float* __restrict__ Bw,
               const float* __restrict__ bias, const float* __restrict__ c_in,
               float* __restrict__ h_out, int NC)
{
    extern __shared__ char smem[];
    float* smemf = (float*)smem;
    const uint32_t sb = smem_to_u32(smem);
    const int tid = threadIdx.x, wid = tid >> 5, lane = tid & 31;
    const int gid = lane >> 2, tig = lane & 3;
    const int warp_m = wid & 3, warp_n = wid >> 2;
    const int n0 = blockIdx.x * NTILE;
    const int m0 = blockIdx.y * 128;

    const float* Ag = A  + m0;            // X[k][m0..]
    const float* Bg = Bw + n0;            // Wt[k][n0..]

    float acc[2][10][4];
    #pragma unroll
    for (int mt = 0; mt < 2; mt++)
        #pragma unroll
        for (int nt = 0; nt < 10; nt++)
            #pragma unroll
            for (int q = 0; q < 4; q++) acc[mt][nt][q] = 0.f;

    // ---- async load helpers ----
    // A chunk: 1024 x 16B ops; B chunk: 1280 x 16B ops
    auto issue_chunk = [&](int c, int stage) {
        uint32_t abase = sb + stage * STAGE_BYTES;
        uint32_t bbase = abase + A_BYTES;
        int k0c = c * 32;
        #pragma unroll
        for (int i = 0; i < 4; i++) {
            int o = i * 256 + tid;          // [0,1024)
            int k = o >> 5, seg = o & 31;
            CPASYNC16(abase + k * (A_STRIDE * 4) + seg * 16,
                      Ag + (size_t)(k0c + k) * BATCH + seg * 4);
        }
        #pragma unroll
        for (int i = 0; i < 5; i++) {
            int o = i * 256 + tid;          // [0,1280)
            int k = o / 40, seg = o - k * 40;
            CPASYNC16(bbase + k * (B_STRIDE * 4) + seg * 16,
                      Bg + (size_t)(k0c + k) * NGATE + seg * 4);
        }
        asm volatile("cp.async.commit_group;" ::: "memory");
    };

    issue_chunk(0, 0);

    const int mrow = warp_m * 32 + gid;         // local row for a0
    const int ncol = warp_n * 80 + gid;         // local col for b0

    for (int c = 0; c < NC; ++c) {
        if (c + 1 < NC) {
            issue_chunk(c + 1, (c + 1) & 1);
            asm volatile("cp.async.wait_group 1;" ::: "memory");
        } else {
            asm volatile("cp.async.wait_group 0;" ::: "memory");
        }
        __syncthreads();

        const float* As = smemf + (c & 1) * (STAGE_BYTES / 4);
        const float* Bs = As + (A_BYTES / 4);

        #pragma unroll
        for (int ks = 0; ks < 4; ks++) {
            int k = ks * 8 + tig;
            uint32_t a[2][4], b[10][2];
            #pragma unroll
            for (int mt = 0; mt < 2; mt++) {
                int r = mrow + mt * 16;
                a[mt][0] = __float_as_uint(As[k * A_STRIDE + r]);
                a[mt][1] = __float_as_uint(As[k * A_STRIDE + r + 8]);
                a[mt][2] = __float_as_uint(As[(k + 4) * A_STRIDE + r]);
                a[mt][3] = __float_as_uint(As[(k + 4) * A_STRIDE + r + 8]);
            }
            #pragma unroll
            for (int nt = 0; nt < 10; nt++) {
                int nn = ncol + nt * 8;
                b[nt][0] = __float_as_uint(Bs[k * B_STRIDE + nn]);
                b[nt][1] = __float_as_uint(Bs[(k + 4) * B_STRIDE + nn]);
            }
            #pragma unroll
            for (int mt = 0; mt < 2; mt++)
                #pragma unroll
                for (int nt = 0; nt < 10; nt++)
                    mma_tf32(acc[mt][nt], a[mt], b[nt]);
        }
        __syncthreads();
    }

    // ---- epilogue: bias + LSTM cell ----
    float* s_c    = smemf;                  // [128][41]
    float* s_h    = smemf + 128 * 41;       // [128][41]
    float* s_bias = smemf + 2 * 128 * 41;   // [160]

    const int u0g = blockIdx.x * 40;        // global unit base
    if (tid < NTILE) {
        int jg = n0 + tid;
        s_bias[tid] = bias[(jg & 3) * LSTM + (jg >> 2)];
    }
    #pragma unroll
    for (int i = 0; i < 5; i++) {
        int idx = i * 256 + tid;            // [0,1280)
        int row = idx / 10, q = idx - row * 10;
        float4 v = *(const float4*)(c_in + (size_t)(m0 + row) * LSTM + u0g + q * 4);
        s_c[row * 41 + q * 4 + 0] = v.x;
        s_c[row * 41 + q * 4 + 1] = v.y;
        s_c[row * 41 + q * 4 + 2] = v.z;
        s_c[row * 41 + q * 4 + 3] = v.w;
    }
    __syncthreads();

    #pragma unroll
    for (int mt = 0; mt < 2; mt++) {
        #pragma unroll
        for (int nt = 0; nt < 10; nt++) {
            float p0 = __shfl_xor_sync(0xffffffffu, acc[mt][nt][0], 1);
            float p1 = __shfl_xor_sync(0xffffffffu, acc[mt][nt][1], 1);
            float p2 = __shfl_xor_sync(0xffffffffu, acc[mt][nt][2], 1);
            float p3 = __shfl_xor_sync(0xffffffffu, acc[mt][nt][3], 1);
            if (!(lane & 1)) {
                int jb = warp_n * 80 + nt * 8 + tig * 2;     // packed col of gate i
                int u  = jb >> 2;                             // unit in CTA
                float bi = s_bias[jb], bf = s_bias[jb + 1];
                float bg = s_bias[jb + 2], bo = s_bias[jb + 3];
                int r0 = warp_m * 32 + mt * 16 + gid;
                #pragma unroll
                for (int hh = 0; hh < 2; hh++) {
                    int r = r0 + hh * 8;
                    float vi = (hh ? acc[mt][nt][2] : acc[mt][nt][0]) + bi;
                    float vf = (hh ? acc[mt][nt][3] : acc[mt][nt][1]) + bf;
                    float vg = (hh ? p2 : p0) + bg;
                    float vo = (hh ? p3 : p1) + bo;
                    float ii = 1.f / (1.f + expf(-vi));
                    float ff = 1.f / (1.f + expf(-vf));
                    float oo = 1.f / (1.f + expf(-vo));
                    float gg = tanhf(vg);
                    float cc = ff * s_c[r * 41 + u] + ii * gg;
                    s_h[r * 41 + u] = oo * tanhf(cc);
                }
            }
        }
    }
    __syncthreads();

    #pragma unroll
    for (int i = 0; i < 5; i++) {
        int idx = i * 256 + tid;
        int row = idx / 10, q = idx - row * 10;
        float4 v;
        v.x = s_h[row * 41 + q * 4 + 0];
        v.y = s_h[row * 41 + q * 4 + 1];
        v.z = s_h[row * 41 + q * 4 + 2];
        v.w = s_h[row * 41 + q * 4 + 3];
        *(float4*)(h_out + (size_t)(m0 + row) * LSTM + u0g + q * 4) = v;
    }
}

// ---------------------------------------------------------------------------
// Attention (unchanged)
// ---------------------------------------------------------------------------
__global__ void attention_kernel(const float* __restrict__ w_prev,
                                 const float* __restrict__ inputs,
                                 const float* __restrict__ h1n,
                                 const float* __restrict__ kappa,
                                 const float* __restrict__ W_attn,
                                 const float* __restrict__ b_attn,
                                 const float* __restrict__ AV,
                                 const int* __restrict__ lens,
                                 float* __restrict__ w_out)
{
    int b = blockIdx.x;
    __shared__ float s_in[ATTN_IN];
    __shared__ float s_par[3 * NATTN];
    __shared__ float s_alpha[NATTN], s_beta[NATTN], s_kap[NATTN];
    __shared__ float s_phi[CHARLEN];
    int t = threadIdx.x;

    for (int i = t; i < 73; i += 128)  s_in[i]      = w_prev[b * 73 + i];
    if (t < 3)                          s_in[73 + t] = inputs[b * 3 + t];
    for (int i = t; i < 400; i += 128) s_in[76 + i] = h1n[b * LSTM + i];
    __syncthreads();

    {
        int out = t >> 2, ln = t & 3;
        float acc = 0.f;
        if (out < 30) {
            const float* wr = W_attn + out * ATTN_IN;
            for (int k = ln; k < ATTN_IN; k += 4) acc = fmaf(s_in[k], wr[k], acc);
        }
        acc += __shfl_down_sync(0xffffffffu, acc, 2);
        acc += __shfl_down_sync(0xffffffffu, acc, 1);
        if (ln == 0 && out < 30) {
            float x = acc + b_attn[out];
            s_par[out] = (x > 20.f) ? x : log1pf(expf(x));
        }
    }
    __syncthreads();

    if (t < NATTN) {
        s_alpha[t] = s_par[t];
        s_beta[t]  = fmaxf(s_par[NATTN + t], 0.01f);
        s_kap[t]   = kappa[b * NATTN + t] + s_par[2 * NATTN + t] * 0.04f;
    }
    __syncthreads();

    int len = lens[b];
    if (t < CHARLEN) {
        float u = (float)t;
        float phi = 0.f;
        #pragma unroll
        for (int i = 0; i < NATTN; i++) {
            float d = s_kap[i] - u;
            phi += s_alpha[i] * expf(-d * d / s_beta[i]);
        }
        s_phi[t] = (t < len) ? phi : 0.f;
    }
    __syncthreads();

    for (int v = t; v < VOCAB; v += 128) {
        float acc = 0.f;
        const float* av = AV + (size_t)b * (CHARLEN * VOCAB) + v;
        #pragma unroll 8
        for (int c = 0; c < CHARLEN; c++) acc = fmaf(s_phi[c], av[c * VOCAB], acc);
        w_out[b * VOCAB + v] = acc;
    }
}

// ---------------------------------------------------------------------------
// Launch
// ---------------------------------------------------------------------------
extern "C" void kernel_launch(void* const* d_in, const int* in_sizes, int n_in,
                              void* d_out, int out_size)
{
    const float* inputs = (const float*)d_in[0];
    const float* h1     = (const float*)d_in[1];
    const float* c1     = (const float*)d_in[2];
    const float* h2     = (const float*)d_in[3];
    const float* c2     = (const float*)d_in[4];
    const float* h3     = (const float*)d_in[5];
    const float* c3     = (const float*)d_in[6];
    const float* kappa  = (const float*)d_in[7];
    const float* w_prev = (const float*)d_in[8];
    const float* AV     = (const float*)d_in[9];
    const int*   lens   = (const int*)  d_in[10];
    const float* W_ih1  = (const float*)d_in[11];
    const float* W_hh1  = (const float*)d_in[12];
    const float* b1     = (const float*)d_in[13];
    const float* W_attn = (const float*)d_in[14];
    const float* b_attn = (const float*)d_in[15];
    const float* W_ih2  = (const float*)d_in[16];
    const float* W_hh2  = (const float*)d_in[17];
    const float* b2     = (const float*)d_in[18];
    const float* W_ih3  = (const float*)d_in[19];
    const float* W_hh3  = (const float*)d_in[20];
    const float* b3     = (const float*)d_in[21];
    float* out = (float*)d_out;

    float *Wt1, *Wt2, *Wt3, *X, *h1n, *h2n, *wbuf;
    cudaGetSymbolAddress((void**)&Wt1,  g_Wt1);
    cudaGetSymbolAddress((void**)&Wt2,  g_Wt2);
    cudaGetSymbolAddress((void**)&Wt3,  g_Wt3);
    cudaGetSymbolAddress((void**)&X,    g_X);
    cudaGetSymbolAddress((void**)&h1n,  g_h1n);
    cudaGetSymbolAddress((void**)&h2n,  g_h2n);
    cudaGetSymbolAddress((void**)&wbuf, g_w);

    cudaFuncSetAttribute(gemm_lstm, cudaFuncAttributeMaxDynamicSharedMemorySize, SMEM_GEMM);

    dim3 tp(32, 8);
    pack_w_t<<<dim3(K1PAD  / 32, NGATE / 32), tp>>>(W_ih1, W_hh1, Wt1, 76,  K1PAD);
    pack_w_t<<<dim3(K23PAD / 32, NGATE / 32), tp>>>(W_ih2, W_hh2, Wt2, 476, K23PAD);
    pack_w_t<<<dim3(K23PAD / 32, NGATE / 32), tp>>>(W_ih3, W_hh3, Wt3, 476, K23PAD);

    dim3 ggrid(NGATE / NTILE, BATCH / 128);   // (10, 32)

    // LSTM 1
    pack_x1_t<<<dim3(K1PAD / 32, BATCH / 32), tp>>>(w_prev, inputs, h1, X);
    gemm_lstm<<<ggrid, 256, SMEM_GEMM>>>(X, Wt1, b1, c1, h1n, K1PAD / 32);

    // Attention
    attention_kernel<<<BATCH, 128>>>(w_prev, inputs, h1n, kappa, W_attn, b_attn,
                                     AV, lens, wbuf);

    // LSTM 2
    pack_x23_t<<<dim3(K23PAD / 32, BATCH / 32), tp>>>(inputs, h1n, wbuf, h2, X);
    gemm_lstm<<<ggrid, 256, SMEM_GEMM>>>(X, Wt2, b2, c2, h2n, K23PAD / 32);

    // LSTM 3
    pack_x23_t<<<dim3(K23PAD / 32, BATCH / 32), tp>>>(inputs, h2n, wbuf, h3, X);
    gemm_lstm<<<ggrid, 256, SMEM_GEMM>>>(X, Wt3, b3, c3, out, K23PAD / 32);
}

// round 4
// speedup vs baseline: 2.7261x; 1.4037x over previous
#include <cuda_runtime.h>
#include <cuda_bf16.h>
#include <math.h>
#include <stdint.h>

// ---------------------------------------------------------------------------
// Problem constants
// ---------------------------------------------------------------------------
#define BATCH   4096
#define LSTM    400
#define VOCAB   73
#define NATTN   10
#define CHARLEN 64
#define NGATE   1600
#define K1PAD   480
#define K23PAD  896
#define ATTN_IN 476
#define NTILE   160
#define MTILE   64

// ---------------------------------------------------------------------------
// Scratch (device globals). X row-major [B][KPAD]; Wt row-major [np][KPAD],
// np = unit*4 + gate (gate-interleaved).
// ---------------------------------------------------------------------------
__device__ float g_Wt1[NGATE * K23PAD];
__device__ float g_Wt2[NGATE * K23PAD];
__device__ float g_Wt3[NGATE * K23PAD];
__device__ float g_X  [BATCH * K23PAD];
__device__ float g_h1n[BATCH * LSTM];
__device__ float g_h2n[BATCH * LSTM];
__device__ float g_w  [BATCH * VOCAB];

__device__ __forceinline__ float to_tf32(float x) {
    float r; asm("cvt.rna.tf32.f32 %0, %1;" : "=f"(r) : "f"(x)); return r;
}

#define CPASYNC16(dst, src) \
    asm volatile("cp.async.cg.shared.global [%0], [%1], 16;" :: "r"(dst), "l"(src) : "memory")

__device__ __forceinline__ uint32_t smem_to_u32(const void* p) {
    uint32_t a;
    asm("{ .reg .u64 t; cvta.to.shared.u64 t, %1; cvt.u32.u64 %0, t; }" : "=r"(a) : "l"(p));
    return a;
}

__device__ __forceinline__ void mma_tf32(float* d, const uint32_t* a, const uint32_t* b) {
    asm volatile(
        "mma.sync.aligned.m16n8k8.row.col.f32.tf32.tf32.f32 "
        "{%0,%1,%2,%3}, {%4,%5,%6,%7}, {%8,%9}, {%0,%1,%2,%3};"
        : "+f"(d[0]), "+f"(d[1]), "+f"(d[2]), "+f"(d[3])
        : "r"(a[0]), "r"(a[1]), "r"(a[2]), "r"(a[3]), "r"(b[0]), "r"(b[1]));
}

// ---------------------------------------------------------------------------
// Packs: transpose-free, fully coalesced elementwise copies with tf32 round.
// ---------------------------------------------------------------------------
__global__ void pack_w(const float* __restrict__ Wih, const float* __restrict__ Whh,
                       float* __restrict__ Wt, int in_w, int kpad)
{
    int idx = blockIdx.x * blockDim.x + threadIdx.x;
    if (idx >= NGATE * kpad) return;
    int np = idx / kpad, k = idx - np * kpad;
    int n = (np & 3) * LSTM + (np >> 2);
    float v = 0.f;
    if (k < in_w)              v = Wih[n * in_w + k];
    else if (k < in_w + LSTM)  v = Whh[n * LSTM + (k - in_w)];
    Wt[idx] = to_tf32(v);
}

__global__ void pack_x1(const float* __restrict__ w_prev, const float* __restrict__ inputs,
                        const float* __restrict__ h1, float* __restrict__ X)
{
    int idx = blockIdx.x * blockDim.x + threadIdx.x;
    if (idx >= BATCH * K1PAD) return;
    int b = idx / K1PAD, c = idx - b * K1PAD;
    float v;
    if      (c < 73)  v = w_prev[b * 73 + c];
    else if (c < 76)  v = inputs[b * 3 + (c - 73)];
    else if (c < 476) v = h1[b * LSTM + (c - 76)];
    else              v = 0.f;
    X[idx] = to_tf32(v);
}

__global__ void pack_x23(const float* __restrict__ inputs, const float* __restrict__ h,
                         const float* __restrict__ w, const float* __restrict__ hrec,
                         float* __restrict__ X)
{
    int idx = blockIdx.x * blockDim.x + threadIdx.x;
    if (idx >= BATCH * K23PAD) return;
    int b = idx / K23PAD, c = idx - b * K23PAD;
    float v;
    if      (c < 3)   v = inputs[b * 3 + c];
    else if (c < 403) v = h[b * LSTM + (c - 3)];
    else if (c < 476) v = w[b * VOCAB + (c - 403)];
    else if (c < 876) v = hrec[b * LSTM + (c - 476)];
    else              v = 0.f;
    X[idx] = to_tf32(v);
}

// ---------------------------------------------------------------------------
// Fused tf32 mma.sync GEMM + LSTM epilogue.
// CTA tile 64(M) x 160(N), BK=32, 8 warps (2M x 4N), warp tile 32x40.
// Both operands row-major in SMEM with stride 36 floats (36 mod 32 == 4):
// fragment LDS banks = 4*gid + tig -> exact permutation, conflict-free.
// 2 CTAs/SM (regs < 128, smem 63 KB).
// ---------------------------------------------------------------------------
#define SMSTRIDE 36
#define A_BYTES  (MTILE * SMSTRIDE * 4)      // 9216
#define B_BYTES  (NTILE * SMSTRIDE * 4)      // 23040
#define STAGE_BYTES (A_BYTES + B_BYTES)      // 32256
#define SMEM_GEMM (2 * STAGE_BYTES)          // 64512

__global__ __launch_bounds__(256, 2)
void gemm_lstm(const float* __restrict__ A, const float* __restrict__ Bw,
               const float* __restrict__ bias, const float* __restrict__ c_in,
               float* __restrict__ h_out, int KPAD, int NC)
{
    extern __shared__ char smem[];
    float* smemf = (float*)smem;
    const uint32_t sb = smem_to_u32(smem);
    const int tid = threadIdx.x, wid = tid >> 5, lane = tid & 31;
    const int gid = lane >> 2, tig = lane & 3;
    const int warp_m = wid & 1, warp_n = wid >> 1;
    const int n0 = blockIdx.x * NTILE;
    const int m0 = blockIdx.y * MTILE;

    const float* Ag = A  + (size_t)m0 * KPAD;
    const float* Bg = Bw + (size_t)n0 * KPAD;

    float acc[2][5][4];
    #pragma unroll
    for (int mt = 0; mt < 2; mt++)
        #pragma unroll
        for (int nt = 0; nt < 5; nt++)
            #pragma unroll
            for (int q = 0; q < 4; q++) acc[mt][nt][q] = 0.f;

    // per chunk: A 64 rows x 8 x 16B = 512 ops; B 160 rows x 8 = 1280 ops
    auto issue_chunk = [&](int c, int stage) {
        uint32_t abase = sb + stage * STAGE_BYTES;
        uint32_t bbase = abase + A_BYTES;
        int k0 = c * 32;
        #pragma unroll
        for (int i = 0; i < 2; i++) {
            int o = i * 256 + tid;          // [0,512)
            int row = o >> 3, seg = o & 7;
            CPASYNC16(abase + row * (SMSTRIDE * 4) + seg * 16,
                      Ag + (size_t)row * KPAD + k0 + seg * 4);
        }
        #pragma unroll
        for (int i = 0; i < 5; i++) {
            int o = i * 256 + tid;          // [0,1280)
            int row = o >> 3, seg = o & 7;
            CPASYNC16(bbase + row * (SMSTRIDE * 4) + seg * 16,
                      Bg + (size_t)row * KPAD + k0 + seg * 4);
        }
        asm volatile("cp.async.commit_group;" ::: "memory");
    };

    issue_chunk(0, 0);

    const int mrow = warp_m * 32 + gid;
    const int ncol = warp_n * 40 + gid;

    #pragma unroll 1
    for (int c = 0; c < NC; ++c) {
        if (c + 1 < NC) {
            issue_chunk(c + 1, (c + 1) & 1);
            asm volatile("cp.async.wait_group 1;" ::: "memory");
        } else {
            asm volatile("cp.async.wait_group 0;" ::: "memory");
        }
        __syncthreads();

        const float* As = smemf + (c & 1) * (STAGE_BYTES / 4);
        const float* Bs = As + (A_BYTES / 4);

        #pragma unroll
        for (int ks = 0; ks < 4; ks++) {
            int k = ks * 8 + tig;
            uint32_t a[2][4], b[5][2];
            #pragma unroll
            for (int mt = 0; mt < 2; mt++) {
                int r = mrow + mt * 16;
                a[mt][0] = __float_as_uint(As[r * SMSTRIDE + k]);
                a[mt][1] = __float_as_uint(As[(r + 8) * SMSTRIDE + k]);
                a[mt][2] = __float_as_uint(As[r * SMSTRIDE + k + 4]);
                a[mt][3] = __float_as_uint(As[(r + 8) * SMSTRIDE + k + 4]);
            }
            #pragma unroll
            for (int nt = 0; nt < 5; nt++) {
                int nn = ncol + nt * 8;
                b[nt][0] = __float_as_uint(Bs[nn * SMSTRIDE + k]);
                b[nt][1] = __float_as_uint(Bs[nn * SMSTRIDE + k + 4]);
            }
            #pragma unroll
            for (int mt = 0; mt < 2; mt++)
                #pragma unroll
                for (int nt = 0; nt < 5; nt++)
                    mma_tf32(acc[mt][nt], a[mt], b[nt]);
        }
        __syncthreads();
    }

    // ---- epilogue: bias + LSTM cell ----
    float* s_c    = smemf;                  // [64][41]
    float* s_h    = smemf + 64 * 41;        // [64][41]
    float* s_bias = smemf + 2 * 64 * 41;    // [160]

    const int u0g = blockIdx.x * 40;
    if (tid < NTILE) {
        int jg = n0 + tid;
        s_bias[tid] = bias[(jg & 3) * LSTM + (jg >> 2)];
    }
    #pragma unroll
    for (int i = 0; i < 3; i++) {
        int idx = i * 256 + tid;            // [0,640)
        if (idx < 640) {
            int row = idx / 10, q = idx - row * 10;
            float4 v = *(const float4*)(c_in + (size_t)(m0 + row) * LSTM + u0g + q * 4);
            s_c[row * 41 + q * 4 + 0] = v.x;
            s_c[row * 41 + q * 4 + 1] = v.y;
            s_c[row * 41 + q * 4 + 2] = v.z;
            s_c[row * 41 + q * 4 + 3] = v.w;
        }
    }
    __syncthreads();

    #pragma unroll
    for (int mt = 0; mt < 2; mt++) {
        #pragma unroll
        for (int nt = 0; nt < 5; nt++) {
            float p0 = __shfl_xor_sync(0xffffffffu, acc[mt][nt][0], 1);
            float p1 = __shfl_xor_sync(0xffffffffu, acc[mt][nt][1], 1);
            float p2 = __shfl_xor_sync(0xffffffffu, acc[mt][nt][2], 1);
            float p3 = __shfl_xor_sync(0xffffffffu, acc[mt][nt][3], 1);
            if (!(lane & 1)) {
                int jb = warp_n * 40 + nt * 8 + tig * 2;   // packed col (gate i)
                int u  = jb >> 2;                           // unit within CTA
                float bi = s_bias[jb], bf = s_bias[jb + 1];
                float bg = s_bias[jb + 2], bo = s_bias[jb + 3];
                int r0 = warp_m * 32 + mt * 16 + gid;
                #pragma unroll
                for (int hh = 0; hh < 2; hh++) {
                    int r = r0 + hh * 8;
                    float vi = (hh ? acc[mt][nt][2] : acc[mt][nt][0]) + bi;
                    float vf = (hh ? acc[mt][nt][3] : acc[mt][nt][1]) + bf;
                    float vg = (hh ? p2 : p0) + bg;
                    float vo = (hh ? p3 : p1) + bo;
                    float ii = 1.f / (1.f + expf(-vi));
                    float ff = 1.f / (1.f + expf(-vf));
                    float oo = 1.f / (1.f + expf(-vo));
                    float gg = tanhf(vg);
                    float cc = ff * s_c[r * 41 + u] + ii * gg;
                    s_h[r * 41 + u] = oo * tanhf(cc);
                }
            }
        }
    }
    __syncthreads();

    #pragma unroll
    for (int i = 0; i < 3; i++) {
        int idx = i * 256 + tid;
        if (idx < 640) {
            int row = idx / 10, q = idx - row * 10;
            float4 v;
            v.x = s_h[row * 41 + q * 4 + 0];
            v.y = s_h[row * 41 + q * 4 + 1];
            v.z = s_h[row * 41 + q * 4 + 2];
            v.w = s_h[row * 41 + q * 4 + 3];
            *(float4*)(h_out + (size_t)(m0 + row) * LSTM + u0g + q * 4) = v;
        }
    }
}

// ---------------------------------------------------------------------------
// Attention (unchanged)
// ---------------------------------------------------------------------------
__global__ void attention_kernel(const float* __restrict__ w_prev,
                                 const float* __restrict__ inputs,
                                 const float* __restrict__ h1n,
                                 const float* __restrict__ kappa,
                                 const float* __restrict__ W_attn,
                                 const float* __restrict__ b_attn,
                                 const float* __restrict__ AV,
                                 const int* __restrict__ lens,
                                 float* __restrict__ w_out)
{
    int b = blockIdx.x;
    __shared__ float s_in[ATTN_IN];
    __shared__ float s_par[3 * NATTN];
    __shared__ float s_alpha[NATTN], s_beta[NATTN], s_kap[NATTN];
    __shared__ float s_phi[CHARLEN];
    int t = threadIdx.x;

    for (int i = t; i < 73; i += 128)  s_in[i]      = w_prev[b * 73 + i];
    if (t < 3)                          s_in[73 + t] = inputs[b * 3 + t];
    for (int i = t; i < 400; i += 128) s_in[76 + i] = h1n[b * LSTM + i];
    __syncthreads();

    {
        int out = t >> 2, ln = t & 3;
        float acc = 0.f;
        if (out < 30) {
            const float* wr = W_attn + out * ATTN_IN;
            for (int k = ln; k < ATTN_IN; k += 4) acc = fmaf(s_in[k], wr[k], acc);
        }
        acc += __shfl_down_sync(0xffffffffu, acc, 2);
        acc += __shfl_down_sync(0xffffffffu, acc, 1);
        if (ln == 0 && out < 30) {
            float x = acc + b_attn[out];
            s_par[out] = (x > 20.f) ? x : log1pf(expf(x));
        }
    }
    __syncthreads();

    if (t < NATTN) {
        s_alpha[t] = s_par[t];
        s_beta[t]  = fmaxf(s_par[NATTN + t], 0.01f);
        s_kap[t]   = kappa[b * NATTN + t] + s_par[2 * NATTN + t] * 0.04f;
    }
    __syncthreads();

    int len = lens[b];
    if (t < CHARLEN) {
        float u = (float)t;
        float phi = 0.f;
        #pragma unroll
        for (int i = 0; i < NATTN; i++) {
            float d = s_kap[i] - u;
            phi += s_alpha[i] * expf(-d * d / s_beta[i]);
        }
        s_phi[t] = (t < len) ? phi : 0.f;
    }
    __syncthreads();

    for (int v = t; v < VOCAB; v += 128) {
        float acc = 0.f;
        const float* av = AV + (size_t)b * (CHARLEN * VOCAB) + v;
        #pragma unroll 8
        for (int c = 0; c < CHARLEN; c++) acc = fmaf(s_phi[c], av[c * VOCAB], acc);
        w_out[b * VOCAB + v] = acc;
    }
}

// ---------------------------------------------------------------------------
// Launch
// ---------------------------------------------------------------------------
extern "C" void kernel_launch(void* const* d_in, const int* in_sizes, int n_in,
                              void* d_out, int out_size)
{
    const float* inputs = (const float*)d_in[0];
    const float* h1     = (const float*)d_in[1];
    const float* c1     = (const float*)d_in[2];
    const float* h2     = (const float*)d_in[3];
    const float* c2     = (const float*)d_in[4];
    const float* h3     = (const float*)d_in[5];
    const float* c3     = (const float*)d_in[6];
    const float* kappa  = (const float*)d_in[7];
    const float* w_prev = (const float*)d_in[8];
    const float* AV     = (const float*)d_in[9];
    const int*   lens   = (const int*)  d_in[10];
    const float* W_ih1  = (const float*)d_in[11];
    const float* W_hh1  = (const float*)d_in[12];
    const float* b1     = (const float*)d_in[13];
    const float* W_attn = (const float*)d_in[14];
    const float* b_attn = (const float*)d_in[15];
    const float* W_ih2  = (const float*)d_in[16];
    const float* W_hh2  = (const float*)d_in[17];
    const float* b2     = (const float*)d_in[18];
    const float* W_ih3  = (const float*)d_in[19];
    const float* W_hh3  = (const float*)d_in[20];
    const float* b3     = (const float*)d_in[21];
    float* out = (float*)d_out;

    float *Wt1, *Wt2, *Wt3, *X, *h1n, *h2n, *wbuf;
    cudaGetSymbolAddress((void**)&Wt1,  g_Wt1);
    cudaGetSymbolAddress((void**)&Wt2,  g_Wt2);
    cudaGetSymbolAddress((void**)&Wt3,  g_Wt3);
    cudaGetSymbolAddress((void**)&X,    g_X);
    cudaGetSymbolAddress((void**)&h1n,  g_h1n);
    cudaGetSymbolAddress((void**)&h2n,  g_h2n);
    cudaGetSymbolAddress((void**)&wbuf, g_w);

    cudaFuncSetAttribute(gemm_lstm, cudaFuncAttributeMaxDynamicSharedMemorySize, SMEM_GEMM);

    pack_w<<<(NGATE * K1PAD  + 255) / 256, 256>>>(W_ih1, W_hh1, Wt1, 76,  K1PAD);
    pack_w<<<(NGATE * K23PAD + 255) / 256, 256>>>(W_ih2, W_hh2, Wt2, 476, K23PAD);
    pack_w<<<(NGATE * K23PAD + 255) / 256, 256>>>(W_ih3, W_hh3, Wt3, 476, K23PAD);

    dim3 ggrid(NGATE / NTILE, BATCH / MTILE);   // (10, 64)

    // LSTM 1
    pack_x1<<<(BATCH * K1PAD + 255) / 256, 256>>>(w_prev, inputs, h1, X);
    gemm_lstm<<<ggrid, 256, SMEM_GEMM>>>(X, Wt1, b1, c1, h1n, K1PAD, K1PAD / 32);

    // Attention
    attention_kernel<<<BATCH, 128>>>(w_prev, inputs, h1n, kappa, W_attn, b_attn,
                                     AV, lens, wbuf);

    // LSTM 2
    pack_x23<<<(BATCH * K23PAD + 255) / 256, 256>>>(inputs, h1n, wbuf, h2, X);
    gemm_lstm<<<ggrid, 256, SMEM_GEMM>>>(X, Wt2, b2, c2, h2n, K23PAD, K23PAD / 32);

    // LSTM 3
    pack_x23<<<(BATCH * K23PAD + 255) / 256, 256>>>(inputs, h2n, wbuf, h3, X);
    gemm_lstm<<<ggrid, 256, SMEM_GEMM>>>(X, Wt3, b3, c3, out, K23PAD, K23PAD / 32);
}

// round 5
// speedup vs baseline: 3.9077x; 1.4334x over previous
#include <cuda_runtime.h>
#include <cuda_fp16.h>
#include <math.h>
#include <stdint.h>

// ---------------------------------------------------------------------------
// Problem constants
// ---------------------------------------------------------------------------
#define BATCH   4096
#define LSTM    400
#define VOCAB   73
#define NATTN   10
#define CHARLEN 64
#define NGATE   1600
#define K1PADH  512             // lstm1 K (476) padded to 8 chunks of 64
#define K23PADH 896             // lstm2/3 K (876) padded to 14 chunks of 64
#define ATTN_IN 476
#define NTILE   160
#define MTILE   64

// ---------------------------------------------------------------------------
// Scratch (device globals). X row-major [B][KPADH] half; Wt row-major
// [np][KPADH] half, np = unit*4 + gate (gate-interleaved).
// ---------------------------------------------------------------------------
__device__ __half g_Wt1[NGATE * K1PADH];
__device__ __half g_Wt2[NGATE * K23PADH];
__device__ __half g_Wt3[NGATE * K23PADH];
__device__ __half g_X  [BATCH * K23PADH];
__device__ float  g_h1n[BATCH * LSTM];
__device__ float  g_h2n[BATCH * LSTM];
__device__ float  g_w  [BATCH * VOCAB];

#define CPASYNC16(dst, src) \
    asm volatile("cp.async.cg.shared.global [%0], [%1], 16;" :: "r"(dst), "l"(src) : "memory")

__device__ __forceinline__ uint32_t smem_to_u32(const void* p) {
    uint32_t a;
    asm("{ .reg .u64 t; cvta.to.shared.u64 t, %1; cvt.u32.u64 %0, t; }" : "=r"(a) : "l"(p));
    return a;
}

__device__ __forceinline__ void mma_f16(float* d, const uint32_t* a, const uint32_t* b) {
    asm volatile(
        "mma.sync.aligned.m16n8k16.row.col.f32.f16.f16.f32 "
        "{%0,%1,%2,%3}, {%4,%5,%6,%7}, {%8,%9}, {%0,%1,%2,%3};"
        : "+f"(d[0]), "+f"(d[1]), "+f"(d[2]), "+f"(d[3])
        : "r"(a[0]), "r"(a[1]), "r"(a[2]), "r"(a[3]), "r"(b[0]), "r"(b[1]));
}

// ---------------------------------------------------------------------------
// Packs: transpose-free, coalesced, fp32 -> half
// ---------------------------------------------------------------------------
__global__ void pack_w(const float* __restrict__ Wih, const float* __restrict__ Whh,
                       __half* __restrict__ Wt, int in_w, int kpad)
{
    int idx = blockIdx.x * blockDim.x + threadIdx.x;
    if (idx >= NGATE * kpad) return;
    int np = idx / kpad, k = idx - np * kpad;
    int n = (np & 3) * LSTM + (np >> 2);
    float v = 0.f;
    if (k < in_w)              v = Wih[n * in_w + k];
    else if (k < in_w + LSTM)  v = Whh[n * LSTM + (k - in_w)];
    Wt[idx] = __float2half_rn(v);
}

__global__ void pack_x1(const float* __restrict__ w_prev, const float* __restrict__ inputs,
                        const float* __restrict__ h1, __half* __restrict__ X)
{
    int idx = blockIdx.x * blockDim.x + threadIdx.x;
    if (idx >= BATCH * K1PADH) return;
    int b = idx >> 9, c = idx & 511;
    float v;
    if      (c < 73)  v = w_prev[b * 73 + c];
    else if (c < 76)  v = inputs[b * 3 + (c - 73)];
    else if (c < 476) v = h1[b * LSTM + (c - 76)];
    else              v = 0.f;
    X[idx] = __float2half_rn(v);
}

__global__ void pack_x23(const float* __restrict__ inputs, const float* __restrict__ h,
                         const float* __restrict__ w, const float* __restrict__ hrec,
                         __half* __restrict__ X)
{
    int idx = blockIdx.x * blockDim.x + threadIdx.x;
    if (idx >= BATCH * K23PADH) return;
    int b = idx / K23PADH, c = idx - b * K23PADH;
    float v;
    if      (c < 3)   v = inputs[b * 3 + c];
    else if (c < 403) v = h[b * LSTM + (c - 3)];
    else if (c < 476) v = w[b * VOCAB + (c - 403)];
    else if (c < 876) v = hrec[b * LSTM + (c - 476)];
    else              v = 0.f;
    X[idx] = __float2half_rn(v);
}

// ---------------------------------------------------------------------------
// Fused fp16 mma.sync GEMM + LSTM epilogue.
// CTA 64(M) x 160(N), BK=64 halves, 8 warps (2M x 4N), warp tile 32x40.
// SMEM rows stride 72 halves (36 words, 36 mod 32 == 4): fragment LDS banks
// = 4*gid + tig -> conflict-free. 2 CTAs/SM.
// ---------------------------------------------------------------------------
#define SMSTRH   72                          // halves per smem row
#define A_BYTES  (MTILE * SMSTRH * 2)        // 9216
#define B_BYTES  (NTILE * SMSTRH * 2)        // 23040
#define STAGE_BYTES (A_BYTES + B_BYTES)      // 32256
#define SMEM_GEMM (2 * STAGE_BYTES)          // 64512

__global__ __launch_bounds__(256, 2)
void gemm_lstm(const __half* __restrict__ A, const __half* __restrict__ Bw,
               const float* __restrict__ bias, const float* __restrict__ c_in,
               float* __restrict__ h_out, int KPAD, int NC)
{
    extern __shared__ char smem[];
    float* smemf = (float*)smem;
    const uint32_t sb = smem_to_u32(smem);
    const int tid = threadIdx.x, wid = tid >> 5, lane = tid & 31;
    const int gid = lane >> 2, tig = lane & 3;
    const int warp_m = wid & 1, warp_n = wid >> 1;
    const int n0 = blockIdx.x * NTILE;
    const int m0 = blockIdx.y * MTILE;

    const __half* Ag = A  + (size_t)m0 * KPAD;
    const __half* Bg = Bw + (size_t)n0 * KPAD;

    float acc[2][5][4];
    #pragma unroll
    for (int mt = 0; mt < 2; mt++)
        #pragma unroll
        for (int nt = 0; nt < 5; nt++)
            #pragma unroll
            for (int q = 0; q < 4; q++) acc[mt][nt][q] = 0.f;

    // per chunk: A 64 rows x 8 x 16B = 512 ops; B 160 rows x 8 = 1280 ops
    auto issue_chunk = [&](int c, int stage) {
        uint32_t abase = sb + stage * STAGE_BYTES;
        uint32_t bbase = abase + A_BYTES;
        int k0 = c * 64;
        #pragma unroll
        for (int i = 0; i < 2; i++) {
            int o = i * 256 + tid;
            int row = o >> 3, seg = o & 7;
            CPASYNC16(abase + row * (SMSTRH * 2) + seg * 16,
                      Ag + (size_t)row * KPAD + k0 + seg * 8);
        }
        #pragma unroll
        for (int i = 0; i < 5; i++) {
            int o = i * 256 + tid;
            int row = o >> 3, seg = o & 7;
            CPASYNC16(bbase + row * (SMSTRH * 2) + seg * 16,
                      Bg + (size_t)row * KPAD + k0 + seg * 8);
        }
        asm volatile("cp.async.commit_group;" ::: "memory");
    };

    issue_chunk(0, 0);

    const int mrow = warp_m * 32 + gid;
    const int ncol = warp_n * 40 + gid;

    #pragma unroll 1
    for (int c = 0; c < NC; ++c) {
        if (c + 1 < NC) {
            issue_chunk(c + 1, (c + 1) & 1);
            asm volatile("cp.async.wait_group 1;" ::: "memory");
        } else {
            asm volatile("cp.async.wait_group 0;" ::: "memory");
        }
        __syncthreads();

        const uint32_t* Asw = (const uint32_t*)(smem + (c & 1) * STAGE_BYTES);
        const uint32_t* Bsw = Asw + (A_BYTES / 4);

        #pragma unroll
        for (int ks = 0; ks < 4; ks++) {          // four k16 steps per BK=64
            int k2 = ks * 8 + tig;                // half2-word index in row
            uint32_t a[2][4], b[5][2];
            #pragma unroll
            for (int mt = 0; mt < 2; mt++) {
                int r = mrow + mt * 16;
                a[mt][0] = Asw[r * 36 + k2];
                a[mt][1] = Asw[(r + 8) * 36 + k2];
                a[mt][2] = Asw[r * 36 + k2 + 4];
                a[mt][3] = Asw[(r + 8) * 36 + k2 + 4];
            }
            #pragma unroll
            for (int nt = 0; nt < 5; nt++) {
                int nn = ncol + nt * 8;
                b[nt][0] = Bsw[nn * 36 + k2];
                b[nt][1] = Bsw[nn * 36 + k2 + 4];
            }
            #pragma unroll
            for (int mt = 0; mt < 2; mt++)
                #pragma unroll
                for (int nt = 0; nt < 5; nt++)
                    mma_f16(acc[mt][nt], a[mt], b[nt]);
        }
        __syncthreads();
    }

    // ---- epilogue: bias + LSTM cell ----
    float* s_c    = smemf;                  // [64][41]
    float* s_h    = smemf + 64 * 41;        // [64][41]
    float* s_bias = smemf + 2 * 64 * 41;    // [160]

    const int u0g = blockIdx.x * 40;
    if (tid < NTILE) {
        int jg = n0 + tid;
        s_bias[tid] = bias[(jg & 3) * LSTM + (jg >> 2)];
    }
    #pragma unroll
    for (int i = 0; i < 3; i++) {
        int idx = i * 256 + tid;            // [0,640)
        if (idx < 640) {
            int row = idx / 10, q = idx - row * 10;
            float4 v = *(const float4*)(c_in + (size_t)(m0 + row) * LSTM + u0g + q * 4);
            s_c[row * 41 + q * 4 + 0] = v.x;
            s_c[row * 41 + q * 4 + 1] = v.y;
            s_c[row * 41 + q * 4 + 2] = v.z;
            s_c[row * 41 + q * 4 + 3] = v.w;
        }
    }
    __syncthreads();

    #pragma unroll
    for (int mt = 0; mt < 2; mt++) {
        #pragma unroll
        for (int nt = 0; nt < 5; nt++) {
            float p0 = __shfl_xor_sync(0xffffffffu, acc[mt][nt][0], 1);
            float p1 = __shfl_xor_sync(0xffffffffu, acc[mt][nt][1], 1);
            float p2 = __shfl_xor_sync(0xffffffffu, acc[mt][nt][2], 1);
            float p3 = __shfl_xor_sync(0xffffffffu, acc[mt][nt][3], 1);
            if (!(lane & 1)) {
                int jb = warp_n * 40 + nt * 8 + tig * 2;   // packed col (gate i)
                int u  = jb >> 2;                           // unit within CTA
                float bi = s_bias[jb], bf = s_bias[jb + 1];
                float bg = s_bias[jb + 2], bo = s_bias[jb + 3];
                int r0 = warp_m * 32 + mt * 16 + gid;
                #pragma unroll
                for (int hh = 0; hh < 2; hh++) {
                    int r = r0 + hh * 8;
                    float vi = (hh ? acc[mt][nt][2] : acc[mt][nt][0]) + bi;
                    float vf = (hh ? acc[mt][nt][3] : acc[mt][nt][1]) + bf;
                    float vg = (hh ? p2 : p0) + bg;
                    float vo = (hh ? p3 : p1) + bo;
                    float ii = 1.f / (1.f + expf(-vi));
                    float ff = 1.f / (1.f + expf(-vf));
                    float oo = 1.f / (1.f + expf(-vo));
                    float gg = tanhf(vg);
                    float cc = ff * s_c[r * 41 + u] + ii * gg;
                    s_h[r * 41 + u] = oo * tanhf(cc);
                }
            }
        }
    }
    __syncthreads();

    #pragma unroll
    for (int i = 0; i < 3; i++) {
        int idx = i * 256 + tid;
        if (idx < 640) {
            int row = idx / 10, q = idx - row * 10;
            float4 v;
            v.x = s_h[row * 41 + q * 4 + 0];
            v.y = s_h[row * 41 + q * 4 + 1];
            v.z = s_h[row * 41 + q * 4 + 2];
            v.w = s_h[row * 41 + q * 4 + 3];
            *(float4*)(h_out + (size_t)(m0 + row) * LSTM + u0g + q * 4) = v;
        }
    }
}

// ---------------------------------------------------------------------------
// Attention (fp32, unchanged)
// ---------------------------------------------------------------------------
__global__ void attention_kernel(const float* __restrict__ w_prev,
                                 const float* __restrict__ inputs,
                                 const float* __restrict__ h1n,
                                 const float* __restrict__ kappa,
                                 const float* __restrict__ W_attn,
                                 const float* __restrict__ b_attn,
                                 const float* __restrict__ AV,
                                 const int* __restrict__ lens,
                                 float* __restrict__ w_out)
{
    int b = blockIdx.x;
    __shared__ float s_in[ATTN_IN];
    __shared__ float s_par[3 * NATTN];
    __shared__ float s_alpha[NATTN], s_beta[NATTN], s_kap[NATTN];
    __shared__ float s_phi[CHARLEN];
    int t = threadIdx.x;

    for (int i = t; i < 73; i += 128)  s_in[i]      = w_prev[b * 73 + i];
    if (t < 3)                          s_in[73 + t] = inputs[b * 3 + t];
    for (int i = t; i < 400; i += 128) s_in[76 + i] = h1n[b * LSTM + i];
    __syncthreads();

    {
        int out = t >> 2, ln = t & 3;
        float acc = 0.f;
        if (out < 30) {
            const float* wr = W_attn + out * ATTN_IN;
            for (int k = ln; k < ATTN_IN; k += 4) acc = fmaf(s_in[k], wr[k], acc);
        }
        acc += __shfl_down_sync(0xffffffffu, acc, 2);
        acc += __shfl_down_sync(0xffffffffu, acc, 1);
        if (ln == 0 && out < 30) {
            float x = acc + b_attn[out];
            s_par[out] = (x > 20.f) ? x : log1pf(expf(x));
        }
    }
    __syncthreads();

    if (t < NATTN) {
        s_alpha[t] = s_par[t];
        s_beta[t]  = fmaxf(s_par[NATTN + t], 0.01f);
        s_kap[t]   = kappa[b * NATTN + t] + s_par[2 * NATTN + t] * 0.04f;
    }
    __syncthreads();

    int len = lens[b];
    if (t < CHARLEN) {
        float u = (float)t;
        float phi = 0.f;
        #pragma unroll
        for (int i = 0; i < NATTN; i++) {
            float d = s_kap[i] - u;
            phi += s_alpha[i] * expf(-d * d / s_beta[i]);
        }
        s_phi[t] = (t < len) ? phi : 0.f;
    }
    __syncthreads();

    for (int v = t; v < VOCAB; v += 128) {
        float acc = 0.f;
        const float* av = AV + (size_t)b * (CHARLEN * VOCAB) + v;
        #pragma unroll 8
        for (int c = 0; c < CHARLEN; c++) acc = fmaf(s_phi[c], av[c * VOCAB], acc);
        w_out[b * VOCAB + v] = acc;
    }
}

// ---------------------------------------------------------------------------
// Launch
// ---------------------------------------------------------------------------
extern "C" void kernel_launch(void* const* d_in, const int* in_sizes, int n_in,
                              void* d_out, int out_size)
{
    const float* inputs = (const float*)d_in[0];
    const float* h1     = (const float*)d_in[1];
    const float* c1     = (const float*)d_in[2];
    const float* h2     = (const float*)d_in[3];
    const float* c2     = (const float*)d_in[4];
    const float* h3     = (const float*)d_in[5];
    const float* c3     = (const float*)d_in[6];
    const float* kappa  = (const float*)d_in[7];
    const float* w_prev = (const float*)d_in[8];
    const float* AV     = (const float*)d_in[9];
    const int*   lens   = (const int*)  d_in[10];
    const float* W_ih1  = (const float*)d_in[11];
    const float* W_hh1  = (const float*)d_in[12];
    const float* b1     = (const float*)d_in[13];
    const float* W_attn = (const float*)d_in[14];
    const float* b_attn = (const float*)d_in[15];
    const float* W_ih2  = (const float*)d_in[16];
    const float* W_hh2  = (const float*)d_in[17];
    const float* b2     = (const float*)d_in[18];
    const float* W_ih3  = (const float*)d_in[19];
    const float* W_hh3  = (const float*)d_in[20];
    const float* b3     = (const float*)d_in[21];
    float* out = (float*)d_out;

    __half *Wt1, *Wt2, *Wt3, *X;
    float *h1n, *h2n, *wbuf;
    cudaGetSymbolAddress((void**)&Wt1,  g_Wt1);
    cudaGetSymbolAddress((void**)&Wt2,  g_Wt2);
    cudaGetSymbolAddress((void**)&Wt3,  g_Wt3);
    cudaGetSymbolAddress((void**)&X,    g_X);
    cudaGetSymbolAddress((void**)&h1n,  g_h1n);
    cudaGetSymbolAddress((void**)&h2n,  g_h2n);
    cudaGetSymbolAddress((void**)&wbuf, g_w);

    cudaFuncSetAttribute(gemm_lstm, cudaFuncAttributeMaxDynamicSharedMemorySize, SMEM_GEMM);

    pack_w<<<(NGATE * K1PADH  + 255) / 256, 256>>>(W_ih1, W_hh1, Wt1, 76,  K1PADH);
    pack_w<<<(NGATE * K23PADH + 255) / 256, 256>>>(W_ih2, W_hh2, Wt2, 476, K23PADH);
    pack_w<<<(NGATE * K23PADH + 255) / 256, 256>>>(W_ih3, W_hh3, Wt3, 476, K23PADH);

    dim3 ggrid(NGATE / NTILE, BATCH / MTILE);   // (10, 64)

    // LSTM 1
    pack_x1<<<(BATCH * K1PADH + 255) / 256, 256>>>(w_prev, inputs, h1, X);
    gemm_lstm<<<ggrid, 256, SMEM_GEMM>>>(X, Wt1, b1, c1, h1n, K1PADH, K1PADH / 64);

    // Attention
    attention_kernel<<<BATCH, 128>>>(w_prev, inputs, h1n, kappa, W_attn, b_attn,
                                     AV, lens, wbuf);

    // LSTM 2
    pack_x23<<<(BATCH * K23PADH + 255) / 256, 256>>>(inputs, h1n, wbuf, h2, X);
    gemm_lstm<<<ggrid, 256, SMEM_GEMM>>>(X, Wt2, b2, c2, h2n, K23PADH, K23PADH / 64);

    // LSTM 3
    pack_x23<<<(BATCH * K23PADH + 255) / 256, 256>>>(inputs, h2n, wbuf, h3, X);
    gemm_lstm<<<ggrid, 256, SMEM_GEMM>>>(X, Wt3, b3, c3, out, K23PADH, K23PADH / 64);
}

// round 7
// speedup vs baseline: 3.9653x; 1.0147x over previous
#include <cuda_runtime.h>
#include <cuda_fp16.h>
#include <math.h>
#include <stdint.h>

// ---------------------------------------------------------------------------
// Problem constants
// ---------------------------------------------------------------------------
#define BATCH   4096
#define LSTM    400
#define VOCAB   73
#define NATTN   10
#define CHARLEN 64
#define NGATE   1600
#define K1PADH  512             // lstm1 K (476) padded to 8 chunks of 64
#define K23PADH 896             // lstm2/3 K (876) padded to 14 chunks of 64
#define ATTN_IN 476
#define NTILE   160
#define MTILE   64

// ---------------------------------------------------------------------------
// Scratch (device globals). X row-major [B][KPADH] half; Wt row-major
// [np][KPADH] half, np = unit*4 + gate (gate-interleaved).
// ---------------------------------------------------------------------------
__device__ __half g_Wt1[NGATE * K1PADH];
__device__ __half g_Wt2[NGATE * K23PADH];
__device__ __half g_Wt3[NGATE * K23PADH];
__device__ __half g_X  [BATCH * K23PADH];
__device__ float  g_h1n[BATCH * LSTM];
__device__ float  g_h2n[BATCH * LSTM];
__device__ float  g_w  [BATCH * VOCAB];

#define CPASYNC16(dst, src) \
    asm volatile("cp.async.cg.shared.global [%0], [%1], 16;" :: "r"(dst), "l"(src) : "memory")

__device__ __forceinline__ uint32_t smem_to_u32(const void* p) {
    uint32_t a;
    asm("{ .reg .u64 t; cvta.to.shared.u64 t, %1; cvt.u32.u64 %0, t; }" : "=r"(a) : "l"(p));
    return a;
}

__device__ __forceinline__ void mma_f16(float* d, const uint32_t* a, const uint32_t* b) {
    asm volatile(
        "mma.sync.aligned.m16n8k16.row.col.f32.f16.f16.f32 "
        "{%0,%1,%2,%3}, {%4,%5,%6,%7}, {%8,%9}, {%0,%1,%2,%3};"
        : "+f"(d[0]), "+f"(d[1]), "+f"(d[2]), "+f"(d[3])
        : "r"(a[0]), "r"(a[1]), "r"(a[2]), "r"(a[3]), "r"(b[0]), "r"(b[1]));
}

__device__ __forceinline__ void ldsm_x4(uint32_t& r0, uint32_t& r1, uint32_t& r2,
                                        uint32_t& r3, uint32_t addr) {
    asm volatile("ldmatrix.sync.aligned.m8n8.x4.shared.b16 {%0,%1,%2,%3}, [%4];"
                 : "=r"(r0), "=r"(r1), "=r"(r2), "=r"(r3) : "r"(addr));
}
__device__ __forceinline__ void ldsm_x2(uint32_t& r0, uint32_t& r1, uint32_t addr) {
    asm volatile("ldmatrix.sync.aligned.m8n8.x2.shared.b16 {%0,%1}, [%2];"
                 : "=r"(r0), "=r"(r1) : "r"(addr));
}

// ---------------------------------------------------------------------------
// Packs: transpose-free, coalesced, fp32 -> half
// ---------------------------------------------------------------------------
__global__ void pack_w(const float* __restrict__ Wih, const float* __restrict__ Whh,
                       __half* __restrict__ Wt, int in_w, int kpad)
{
    int idx = blockIdx.x * blockDim.x + threadIdx.x;
    if (idx >= NGATE * kpad) return;
    int np = idx / kpad, k = idx - np * kpad;
    int n = (np & 3) * LSTM + (np >> 2);
    float v = 0.f;
    if (k < in_w)              v = Wih[n * in_w + k];
    else if (k < in_w + LSTM)  v = Whh[n * LSTM + (k - in_w)];
    Wt[idx] = __float2half_rn(v);
}

__global__ void pack_x1(const float* __restrict__ w_prev, const float* __restrict__ inputs,
                        const float* __restrict__ h1, __half* __restrict__ X)
{
    int idx = blockIdx.x * blockDim.x + threadIdx.x;
    if (idx >= BATCH * K1PADH) return;
    int b = idx >> 9, c = idx & 511;
    float v;
    if      (c < 73)  v = w_prev[b * 73 + c];
    else if (c < 76)  v = inputs[b * 3 + (c - 73)];
    else if (c < 476) v = h1[b * LSTM + (c - 76)];
    else              v = 0.f;
    X[idx] = __float2half_rn(v);
}

__global__ void pack_x23(const float* __restrict__ inputs, const float* __restrict__ h,
                         const float* __restrict__ w, const float* __restrict__ hrec,
                         __half* __restrict__ X)
{
    int idx = blockIdx.x * blockDim.x + threadIdx.x;
    if (idx >= BATCH * K23PADH) return;
    int b = idx / K23PADH, c = idx - b * K23PADH;
    float v;
    if      (c < 3)   v = inputs[b * 3 + c];
    else if (c < 403) v = h[b * LSTM + (c - 3)];
    else if (c < 476) v = w[b * VOCAB + (c - 403)];
    else if (c < 876) v = hrec[b * LSTM + (c - 476)];
    else              v = 0.f;
    X[idx] = __float2half_rn(v);
}

// ---------------------------------------------------------------------------
// Fused fp16 mma.sync GEMM + LSTM epilogue.
// CTA 64(M) x 160(N), BK=64 halves, 8 warps (2M x 4N), warp tile 32x40.
// ldmatrix fragment loads; 3-stage cp.async pipeline with race-free ordering:
//   wait(c) -> __syncthreads -> issue(c+2) -> compute(c)
// (the sync separates compute of c-1 from the overwrite of its stage).
// 2 CTAs/SM.
// ---------------------------------------------------------------------------
#define SMSTRH   72                          // halves per smem row
#define A_BYTES  (MTILE * SMSTRH * 2)        // 9216
#define B_BYTES  (NTILE * SMSTRH * 2)        // 23040
#define STAGE_BYTES (A_BYTES + B_BYTES)      // 32256
#define NSTAGE   3
#define SMEM_GEMM (NSTAGE * STAGE_BYTES)     // 96768

__global__ __launch_bounds__(256, 2)
void gemm_lstm(const __half* __restrict__ A, const __half* __restrict__ Bw,
               const float* __restrict__ bias, const float* __restrict__ c_in,
               float* __restrict__ h_out, int KPAD, int NC)
{
    extern __shared__ char smem[];
    float* smemf = (float*)smem;
    const uint32_t sb = smem_to_u32(smem);
    const int tid = threadIdx.x, wid = tid >> 5, lane = tid & 31;
    const int warp_m = wid & 1, warp_n = wid >> 1;
    const int n0 = blockIdx.x * NTILE;
    const int m0 = blockIdx.y * MTILE;

    const __half* Ag = A  + (size_t)m0 * KPAD;
    const __half* Bg = Bw + (size_t)n0 * KPAD;

    float acc[2][5][4];
    #pragma unroll
    for (int mt = 0; mt < 2; mt++)
        #pragma unroll
        for (int nt = 0; nt < 5; nt++)
            #pragma unroll
            for (int q = 0; q < 4; q++) acc[mt][nt][q] = 0.f;

    // ---- ldmatrix per-thread offsets (relative to stage base) ----
    const int lane8 = lane & 7, mat = lane >> 3;
    uint32_t aoff[2], boff[2], boff2;
    #pragma unroll
    for (int mt = 0; mt < 2; mt++) {
        int arow = warp_m * 32 + mt * 16 + (mat & 1) * 8 + lane8;
        int akh  = (mat >> 1) * 8;
        aoff[mt] = (uint32_t)((arow * SMSTRH + akh) * 2);
    }
    #pragma unroll
    for (int p = 0; p < 2; p++) {
        int brow = warp_n * 40 + p * 16 + (mat >> 1) * 8 + lane8;
        int bkh  = (mat & 1) * 8;
        boff[p] = (uint32_t)(A_BYTES + (brow * SMSTRH + bkh) * 2);
    }
    {
        int m2 = (lane >> 3) & 1;
        int brow = warp_n * 40 + 32 + lane8;
        boff2 = (uint32_t)(A_BYTES + (brow * SMSTRH + m2 * 8) * 2);
    }

    // per chunk: A 64 rows x 8 x 16B = 512 ops; B 160 rows x 8 = 1280 ops
    auto issue_chunk = [&](int c, int stage) {
        uint32_t abase = sb + stage * STAGE_BYTES;
        uint32_t bbase = abase + A_BYTES;
        int k0 = c * 64;
        #pragma unroll
        for (int i = 0; i < 2; i++) {
            int o = i * 256 + tid;
            int row = o >> 3, seg = o & 7;
            CPASYNC16(abase + row * (SMSTRH * 2) + seg * 16,
                      Ag + (size_t)row * KPAD + k0 + seg * 8);
        }
        #pragma unroll
        for (int i = 0; i < 5; i++) {
            int o = i * 256 + tid;
            int row = o >> 3, seg = o & 7;
            CPASYNC16(bbase + row * (SMSTRH * 2) + seg * 16,
                      Bg + (size_t)row * KPAD + k0 + seg * 8);
        }
        asm volatile("cp.async.commit_group;" ::: "memory");
    };

    issue_chunk(0, 0);
    if (NC > 1) issue_chunk(1, 1);

    #pragma unroll 1
    for (int c = 0; c < NC; ++c) {
        // wait for chunk c (pending before wait: {c, c+1} -> allow 1; last iter: 0)
        if (c + 1 < NC) {
            asm volatile("cp.async.wait_group 1;" ::: "memory");
        } else {
            asm volatile("cp.async.wait_group 0;" ::: "memory");
        }
        __syncthreads();   // (a) chunk c visible to all; (b) compute of c-1 done
                           //     before its stage is overwritten below.
        if (c + 2 < NC) issue_chunk(c + 2, (c + 2) % NSTAGE);

        const uint32_t sbase = sb + (c % NSTAGE) * STAGE_BYTES;
        #pragma unroll
        for (int ks = 0; ks < 4; ks++) {
            uint32_t koff = sbase + ks * 32;       // 16 halves per k-step
            uint32_t a[2][4], b[5][2];
            ldsm_x4(a[0][0], a[0][1], a[0][2], a[0][3], koff + aoff[0]);
            ldsm_x4(a[1][0], a[1][1], a[1][2], a[1][3], koff + aoff[1]);
            ldsm_x4(b[0][0], b[0][1], b[1][0], b[1][1], koff + boff[0]);
            ldsm_x4(b[2][0], b[2][1], b[3][0], b[3][1], koff + boff[1]);
            ldsm_x2(b[4][0], b[4][1], koff + boff2);
            #pragma unroll
            for (int mt = 0; mt < 2; mt++)
                #pragma unroll
                for (int nt = 0; nt < 5; nt++)
                    mma_f16(acc[mt][nt], a[mt], b[nt]);
        }
    }
    __syncthreads();

    // ---- epilogue: bias + LSTM cell ----
    float* s_c    = smemf;                  // [64][41]
    float* s_h    = smemf + 64 * 41;        // [64][41]
    float* s_bias = smemf + 2 * 64 * 41;    // [160]

    const int u0g = blockIdx.x * 40;
    if (tid < NTILE) {
        int jg = n0 + tid;
        s_bias[tid] = bias[(jg & 3) * LSTM + (jg >> 2)];
    }
    #pragma unroll
    for (int i = 0; i < 3; i++) {
        int idx = i * 256 + tid;            // [0,640)
        if (idx < 640) {
            int row = idx / 10, q = idx - row * 10;
            float4 v = *(const float4*)(c_in + (size_t)(m0 + row) * LSTM + u0g + q * 4);
            s_c[row * 41 + q * 4 + 0] = v.x;
            s_c[row * 41 + q * 4 + 1] = v.y;
            s_c[row * 41 + q * 4 + 2] = v.z;
            s_c[row * 41 + q * 4 + 3] = v.w;
        }
    }
    __syncthreads();

    const int gid = lane >> 2, tig = lane & 3;
    #pragma unroll
    for (int mt = 0; mt < 2; mt++) {
        #pragma unroll
        for (int nt = 0; nt < 5; nt++) {
            float p0 = __shfl_xor_sync(0xffffffffu, acc[mt][nt][0], 1);
            float p1 = __shfl_xor_sync(0xffffffffu, acc[mt][nt][1], 1);
            float p2 = __shfl_xor_sync(0xffffffffu, acc[mt][nt][2], 1);
            float p3 = __shfl_xor_sync(0xffffffffu, acc[mt][nt][3], 1);
            if (!(lane & 1)) {
                int jb = warp_n * 40 + nt * 8 + tig * 2;   // packed col (gate i)
                int u  = jb >> 2;                           // unit within CTA
                float bi = s_bias[jb], bf = s_bias[jb + 1];
                float bg = s_bias[jb + 2], bo = s_bias[jb + 3];
                int r0 = warp_m * 32 + mt * 16 + gid;
                #pragma unroll
                for (int hh = 0; hh < 2; hh++) {
                    int r = r0 + hh * 8;
                    float vi = (hh ? acc[mt][nt][2] : acc[mt][nt][0]) + bi;
                    float vf = (hh ? acc[mt][nt][3] : acc[mt][nt][1]) + bf;
                    float vg = (hh ? p2 : p0) + bg;
                    float vo = (hh ? p3 : p1) + bo;
                    float ii = 1.f / (1.f + expf(-vi));
                    float ff = 1.f / (1.f + expf(-vf));
                    float oo = 1.f / (1.f + expf(-vo));
                    float gg = tanhf(vg);
                    float cc = ff * s_c[r * 41 + u] + ii * gg;
                    s_h[r * 41 + u] = oo * tanhf(cc);
                }
            }
        }
    }
    __syncthreads();

    #pragma unroll
    for (int i = 0; i < 3; i++) {
        int idx = i * 256 + tid;
        if (idx < 640) {
            int row = idx / 10, q = idx - row * 10;
            float4 v;
            v.x = s_h[row * 41 + q * 4 + 0];
            v.y = s_h[row * 41 + q * 4 + 1];
            v.z = s_h[row * 41 + q * 4 + 2];
            v.w = s_h[row * 41 + q * 4 + 3];
            *(float4*)(h_out + (size_t)(m0 + row) * LSTM + u0g + q * 4) = v;
        }
    }
}

// ---------------------------------------------------------------------------
// Attention (fp32, unchanged)
// ---------------------------------------------------------------------------
__global__ void attention_kernel(const float* __restrict__ w_prev,
                                 const float* __restrict__ inputs,
                                 const float* __restrict__ h1n,
                                 const float* __restrict__ kappa,
                                 const float* __restrict__ W_attn,
                                 const float* __restrict__ b_attn,
                                 const float* __restrict__ AV,
                                 const int* __restrict__ lens,
                                 float* __restrict__ w_out)
{
    int b = blockIdx.x;
    __shared__ float s_in[ATTN_IN];
    __shared__ float s_par[3 * NATTN];
    __shared__ float s_alpha[NATTN], s_beta[NATTN], s_kap[NATTN];
    __shared__ float s_phi[CHARLEN];
    int t = threadIdx.x;

    for (int i = t; i < 73; i += 128)  s_in[i]      = w_prev[b * 73 + i];
    if (t < 3)                          s_in[73 + t] = inputs[b * 3 + t];
    for (int i = t; i < 400; i += 128) s_in[76 + i] = h1n[b * LSTM + i];
    __syncthreads();

    {
        int out = t >> 2, ln = t & 3;
        float acc = 0.f;
        if (out < 30) {
            const float* wr = W_attn + out * ATTN_IN;
            for (int k = ln; k < ATTN_IN; k += 4) acc = fmaf(s_in[k], wr[k], acc);
        }
        acc += __shfl_down_sync(0xffffffffu, acc, 2);
        acc += __shfl_down_sync(0xffffffffu, acc, 1);
        if (ln == 0 && out < 30) {
            float x = acc + b_attn[out];
            s_par[out] = (x > 20.f) ? x : log1pf(expf(x));
        }
    }
    __syncthreads();

    if (t < NATTN) {
        s_alpha[t] = s_par[t];
        s_beta[t]  = fmaxf(s_par[NATTN + t], 0.01f);
        s_kap[t]   = kappa[b * NATTN + t] + s_par[2 * NATTN + t] * 0.04f;
    }
    __syncthreads();

    int len = lens[b];
    if (t < CHARLEN) {
        float u = (float)t;
        float phi = 0.f;
        #pragma unroll
        for (int i = 0; i < NATTN; i++) {
            float d = s_kap[i] - u;
            phi += s_alpha[i] * expf(-d * d / s_beta[i]);
        }
        s_phi[t] = (t < len) ? phi : 0.f;
    }
    __syncthreads();

    for (int v = t; v < VOCAB; v += 128) {
        float acc = 0.f;
        const float* av = AV + (size_t)b * (CHARLEN * VOCAB) + v;
        #pragma unroll 8
        for (int c = 0; c < CHARLEN; c++) acc = fmaf(s_phi[c], av[c * VOCAB], acc);
        w_out[b * VOCAB + v] = acc;
    }
}

// ---------------------------------------------------------------------------
// Launch
// ---------------------------------------------------------------------------
extern "C" void kernel_launch(void* const* d_in, const int* in_sizes, int n_in,
                              void* d_out, int out_size)
{
    const float* inputs = (const float*)d_in[0];
    const float* h1     = (const float*)d_in[1];
    const float* c1     = (const float*)d_in[2];
    const float* h2     = (const float*)d_in[3];
    const float* c2     = (const float*)d_in[4];
    const float* h3     = (const float*)d_in[5];
    const float* c3     = (const float*)d_in[6];
    const float* kappa  = (const float*)d_in[7];
    const float* w_prev = (const float*)d_in[8];
    const float* AV     = (const float*)d_in[9];
    const int*   lens   = (const int*)  d_in[10];
    const float* W_ih1  = (const float*)d_in[11];
    const float* W_hh1  = (const float*)d_in[12];
    const float* b1     = (const float*)d_in[13];
    const float* W_attn = (const float*)d_in[14];
    const float* b_attn = (const float*)d_in[15];
    const float* W_ih2  = (const float*)d_in[16];
    const float* W_hh2  = (const float*)d_in[17];
    const float* b2     = (const float*)d_in[18];
    const float* W_ih3  = (const float*)d_in[19];
    const float* W_hh3  = (const float*)d_in[20];
    const float* b3     = (const float*)d_in[21];
    float* out = (float*)d_out;

    __half *Wt1, *Wt2, *Wt3, *X;
    float *h1n, *h2n, *wbuf;
    cudaGetSymbolAddress((void**)&Wt1,  g_Wt1);
    cudaGetSymbolAddress((void**)&Wt2,  g_Wt2);
    cudaGetSymbolAddress((void**)&Wt3,  g_Wt3);
    cudaGetSymbolAddress((void**)&X,    g_X);
    cudaGetSymbolAddress((void**)&h1n,  g_h1n);
    cudaGetSymbolAddress((void**)&h2n,  g_h2n);
    cudaGetSymbolAddress((void**)&wbuf, g_w);

    cudaFuncSetAttribute(gemm_lstm, cudaFuncAttributeMaxDynamicSharedMemorySize, SMEM_GEMM);

    pack_w<<<(NGATE * K1PADH  + 255) / 256, 256>>>(W_ih1, W_hh1, Wt1, 76,  K1PADH);
    pack_w<<<(NGATE * K23PADH + 255) / 256, 256>>>(W_ih2, W_hh2, Wt2, 476, K23PADH);
    pack_w<<<(NGATE * K23PADH + 255) / 256, 256>>>(W_ih3, W_hh3, Wt3, 476, K23PADH);

    dim3 ggrid(NGATE / NTILE, BATCH / MTILE);   // (10, 64)

    // LSTM 1
    pack_x1<<<(BATCH * K1PADH + 255) / 256, 256>>>(w_prev, inputs, h1, X);
    gemm_lstm<<<ggrid, 256, SMEM_GEMM>>>(X, Wt1, b1, c1, h1n, K1PADH, K1PADH / 64);

    // Attention
    attention_kernel<<<BATCH, 128>>>(w_prev, inputs, h1n, kappa, W_attn, b_attn,
                                     AV, lens, wbuf);

    // LSTM 2
    pack_x23<<<(BATCH * K23PADH + 255) / 256, 256>>>(inputs, h1n, wbuf, h2, X);
    gemm_lstm<<<ggrid, 256, SMEM_GEMM>>>(X, Wt2, b2, c2, h2n, K23PADH, K23PADH / 64);

    // LSTM 3
    pack_x23<<<(BATCH * K23PADH + 255) / 256, 256>>>(inputs, h2n, wbuf, h3, X);
    gemm_lstm<<<ggrid, 256, SMEM_GEMM>>>(X, Wt3, b3, c3, out, K23PADH, K23PADH / 64);
}

// round 8
// speedup vs baseline: 4.3902x; 1.1072x over previous
#include <cuda_runtime.h>
#include <cuda_fp16.h>
#include <math.h>
#include <stdint.h>

// ---------------------------------------------------------------------------
// Problem constants
// ---------------------------------------------------------------------------
#define BATCH   4096
#define LSTM    400
#define VOCAB   73
#define NATTN   10
#define CHARLEN 64
#define NGATE   1600
#define K1PADH  512
#define K23PADH 896
#define ATTN_IN 476
#define NTILE   80              // 20 units per CTA tile
#define MTILE   64

// ---------------------------------------------------------------------------
// Scratch. X row-major half; Wt row-major [np][KPAD] half, np = unit*4+gate.
// X2/X3 col map: [0,3)=inputs, [3,403)=h(prev layer, epilogue), [403,476)=w
// (attention), [476,876)=hrec, [876,896)=0.
// ---------------------------------------------------------------------------
__device__ __half g_Wt1[NGATE * K1PADH];
__device__ __half g_Wt2[NGATE * K23PADH];
__device__ __half g_Wt3[NGATE * K23PADH];
__device__ __half g_X1 [BATCH * K1PADH];
__device__ __half g_X2 [BATCH * K23PADH];
__device__ __half g_X3 [BATCH * K23PADH];
__device__ float  g_h1n[BATCH * LSTM];

#define CPASYNC16(dst, src) \
    asm volatile("cp.async.cg.shared.global [%0], [%1], 16;" :: "r"(dst), "l"(src) : "memory")

__device__ __forceinline__ uint32_t smem_to_u32(const void* p) {
    uint32_t a;
    asm("{ .reg .u64 t; cvta.to.shared.u64 t, %1; cvt.u32.u64 %0, t; }" : "=r"(a) : "l"(p));
    return a;
}

__device__ __forceinline__ void mma_f16(float* d, const uint32_t* a, const uint32_t* b) {
    asm volatile(
        "mma.sync.aligned.m16n8k16.row.col.f32.f16.f16.f32 "
        "{%0,%1,%2,%3}, {%4,%5,%6,%7}, {%8,%9}, {%0,%1,%2,%3};"
        : "+f"(d[0]), "+f"(d[1]), "+f"(d[2]), "+f"(d[3])
        : "r"(a[0]), "r"(a[1]), "r"(a[2]), "r"(a[3]), "r"(b[0]), "r"(b[1]));
}

__device__ __forceinline__ void ldsm_x4(uint32_t& r0, uint32_t& r1, uint32_t& r2,
                                        uint32_t& r3, uint32_t addr) {
    asm volatile("ldmatrix.sync.aligned.m8n8.x4.shared.b16 {%0,%1,%2,%3}, [%4];"
                 : "=r"(r0), "=r"(r1), "=r"(r2), "=r"(r3) : "r"(addr));
}
__device__ __forceinline__ void ldsm_x2(uint32_t& r0, uint32_t& r1, uint32_t addr) {
    asm volatile("ldmatrix.sync.aligned.m8n8.x2.shared.b16 {%0,%1}, [%2];"
                 : "=r"(r0), "=r"(r1) : "r"(addr));
}

// ---------------------------------------------------------------------------
// Packs
// ---------------------------------------------------------------------------
__global__ void pack_w(const float* __restrict__ Wih, const float* __restrict__ Whh,
                       __half* __restrict__ Wt, int in_w, int kpad)
{
    int idx = blockIdx.x * blockDim.x + threadIdx.x;
    if (idx >= NGATE * kpad) return;
    int np = idx / kpad, k = idx - np * kpad;
    int n = (np & 3) * LSTM + (np >> 2);
    float v = 0.f;
    if (k < in_w)              v = Wih[n * in_w + k];
    else if (k < in_w + LSTM)  v = Whh[n * LSTM + (k - in_w)];
    Wt[idx] = __float2half_rn(v);
}

__global__ void pack_x1(const float* __restrict__ w_prev, const float* __restrict__ inputs,
                        const float* __restrict__ h1, __half* __restrict__ X)
{
    int idx = blockIdx.x * blockDim.x + threadIdx.x;
    if (idx >= BATCH * K1PADH) return;
    int b = idx >> 9, c = idx & 511;
    float v;
    if      (c < 73)  v = w_prev[b * 73 + c];
    else if (c < 76)  v = inputs[b * 3 + (c - 73)];
    else if (c < 476) v = h1[b * LSTM + (c - 76)];
    else              v = 0.f;
    X[idx] = __float2half_rn(v);
}

// fills static columns of X2 (hrec=h2) and X3 (hrec=h3): inputs, hrec, zero pad.
// cols [3,476) are produced later by epilogue/attention.
__global__ void pack_static23(const float* __restrict__ inputs, const float* __restrict__ h2,
                              const float* __restrict__ h3,
                              __half* __restrict__ X2, __half* __restrict__ X3)
{
    int idx = blockIdx.x * blockDim.x + threadIdx.x;
    if (idx >= BATCH * K23PADH) return;
    int b = idx / K23PADH, c = idx - b * K23PADH;
    if (c >= 3 && c < 476) return;
    if (c < 3) {
        __half v = __float2half_rn(inputs[b * 3 + c]);
        X2[idx] = v; X3[idx] = v;
    } else if (c < 876) {
        X2[idx] = __float2half_rn(h2[b * LSTM + (c - 476)]);
        X3[idx] = __float2half_rn(h3[b * LSTM + (c - 476)]);
    } else {
        X2[idx] = __float2half_rn(0.f);
        X3[idx] = __float2half_rn(0.f);
    }
}

// ---------------------------------------------------------------------------
// Fused fp16 mma.sync GEMM + LSTM epilogue.
// CTA 64(M) x 80(N), BK=64 halves, 8 warps (4M x 2N), warp tile 16x40.
// ldmatrix fragments, 3-stage cp.async pipeline (race-free ordering),
// 3 CTAs/SM. Epilogue writes h as fp32 (h_f32) and/or half into next-layer X
// at column offset 3 (h_h16).
// ---------------------------------------------------------------------------
#define SMSTRH   72
#define A_BYTES  (MTILE * SMSTRH * 2)        // 9216
#define B_BYTES  (NTILE * SMSTRH * 2)        // 11520
#define STAGE_BYTES (A_BYTES + B_BYTES)      // 20736
#define NSTAGE   3
#define SMEM_GEMM (NSTAGE * STAGE_BYTES)     // 62208

__global__ __launch_bounds__(256, 3)
void gemm_lstm(const __half* __restrict__ A, const __half* __restrict__ Bw,
               const float* __restrict__ bias, const float* __restrict__ c_in,
               float* __restrict__ h_f32, __half* __restrict__ h_h16,
               int KPAD, int NC)
{
    extern __shared__ char smem[];
    float* smemf = (float*)smem;
    const uint32_t sb = smem_to_u32(smem);
    const int tid = threadIdx.x, wid = tid >> 5, lane = tid & 31;
    const int warp_m = wid & 3, warp_n = wid >> 2;
    const int n0 = blockIdx.x * NTILE;
    const int m0 = blockIdx.y * MTILE;

    const __half* Ag = A  + (size_t)m0 * KPAD;
    const __half* Bg = Bw + (size_t)n0 * KPAD;

    float acc[5][4];
    #pragma unroll
    for (int nt = 0; nt < 5; nt++)
        #pragma unroll
        for (int q = 0; q < 4; q++) acc[nt][q] = 0.f;

    // ---- ldmatrix per-thread offsets (relative to stage base) ----
    const int lane8 = lane & 7, mat = lane >> 3;
    uint32_t aoff, boff[2], boff2;
    {
        int arow = warp_m * 16 + (mat & 1) * 8 + lane8;
        aoff = (uint32_t)((arow * SMSTRH + (mat >> 1) * 8) * 2);
    }
    #pragma unroll
    for (int p = 0; p < 2; p++) {
        int brow = warp_n * 40 + p * 16 + (mat >> 1) * 8 + lane8;
        boff[p] = (uint32_t)(A_BYTES + (brow * SMSTRH + (mat & 1) * 8) * 2);
    }
    {
        int m2 = (lane >> 3) & 1;
        int brow = warp_n * 40 + 32 + lane8;
        boff2 = (uint32_t)(A_BYTES + (brow * SMSTRH + m2 * 8) * 2);
    }

    // per chunk: A 64 rows x 8 x 16B = 512 ops; B 80 rows x 8 = 640 ops
    auto issue_chunk = [&](int c, int stage) {
        uint32_t abase = sb + stage * STAGE_BYTES;
        uint32_t bbase = abase + A_BYTES;
        int k0 = c * 64;
        #pragma unroll
        for (int i = 0; i < 2; i++) {
            int o = i * 256 + tid;
            int row = o >> 3, seg = o & 7;
            CPASYNC16(abase + row * (SMSTRH * 2) + seg * 16,
                      Ag + (size_t)row * KPAD + k0 + seg * 8);
        }
        #pragma unroll
        for (int i = 0; i < 3; i++) {
            int o = i * 256 + tid;
            if (o < 640) {
                int row = o >> 3, seg = o & 7;
                CPASYNC16(bbase + row * (SMSTRH * 2) + seg * 16,
                          Bg + (size_t)row * KPAD + k0 + seg * 8);
            }
        }
        asm volatile("cp.async.commit_group;" ::: "memory");
    };

    issue_chunk(0, 0);
    if (NC > 1) issue_chunk(1, 1);

    #pragma unroll 1
    for (int c = 0; c < NC; ++c) {
        if (c + 1 < NC) {
            asm volatile("cp.async.wait_group 1;" ::: "memory");
        } else {
            asm volatile("cp.async.wait_group 0;" ::: "memory");
        }
        __syncthreads();   // chunk c visible; compute of c-1 done before overwrite
        if (c + 2 < NC) issue_chunk(c + 2, (c + 2) % NSTAGE);

        const uint32_t sbase = sb + (c % NSTAGE) * STAGE_BYTES;
        #pragma unroll
        for (int ks = 0; ks < 4; ks++) {
            uint32_t koff = sbase + ks * 32;
            uint32_t a[4], b[5][2];
            ldsm_x4(a[0], a[1], a[2], a[3], koff + aoff);
            ldsm_x4(b[0][0], b[0][1], b[1][0], b[1][1], koff + boff[0]);
            ldsm_x4(b[2][0], b[2][1], b[3][0], b[3][1], koff + boff[1]);
            ldsm_x2(b[4][0], b[4][1], koff + boff2);
            #pragma unroll
            for (int nt = 0; nt < 5; nt++)
                mma_f16(acc[nt], a, b[nt]);
        }
    }
    __syncthreads();

    // ---- epilogue: bias + LSTM cell ----
    float* s_c    = smemf;                   // [64][21]
    float* s_h    = smemf + 64 * 21;         // [64][21]
    float* s_bias = smemf + 2 * 64 * 21;     // [80]

    const int u0g = blockIdx.x * 20;         // global unit base
    if (tid < NTILE) {
        int jg = n0 + tid;
        s_bias[tid] = bias[(jg & 3) * LSTM + (jg >> 2)];
    }
    #pragma unroll
    for (int i = 0; i < 2; i++) {
        int idx = i * 256 + tid;             // [0,320)
        if (idx < 320) {
            int row = idx / 5, q = idx - row * 5;
            float4 v = *(const float4*)(c_in + (size_t)(m0 + row) * LSTM + u0g + q * 4);
            s_c[row * 21 + q * 4 + 0] = v.x;
            s_c[row * 21 + q * 4 + 1] = v.y;
            s_c[row * 21 + q * 4 + 2] = v.z;
            s_c[row * 21 + q * 4 + 3] = v.w;
        }
    }
    __syncthreads();

    const int gid = lane >> 2, tig = lane & 3;
    #pragma unroll
    for (int nt = 0; nt < 5; nt++) {
        float p0 = __shfl_xor_sync(0xffffffffu, acc[nt][0], 1);
        float p1 = __shfl_xor_sync(0xffffffffu, acc[nt][1], 1);
        float p2 = __shfl_xor_sync(0xffffffffu, acc[nt][2], 1);
        float p3 = __shfl_xor_sync(0xffffffffu, acc[nt][3], 1);
        if (!(lane & 1)) {
            int jb = warp_n * 40 + nt * 8 + tig * 2;
            int u  = jb >> 2;
            float bi = s_bias[jb], bf = s_bias[jb + 1];
            float bg = s_bias[jb + 2], bo = s_bias[jb + 3];
            int r0 = warp_m * 16 + gid;
            #pragma unroll
            for (int hh = 0; hh < 2; hh++) {
                int r = r0 + hh * 8;
                float vi = (hh ? acc[nt][2] : acc[nt][0]) + bi;
                float vf = (hh ? acc[nt][3] : acc[nt][1]) + bf;
                float vg = (hh ? p2 : p0) + bg;
                float vo = (hh ? p3 : p1) + bo;
                float ii = 1.f / (1.f + expf(-vi));
                float ff = 1.f / (1.f + expf(-vf));
                float oo = 1.f / (1.f + expf(-vo));
                float gg = tanhf(vg);
                float cc = ff * s_c[r * 21 + u] + ii * gg;
                s_h[r * 21 + u] = oo * tanhf(cc);
            }
        }
    }
    __syncthreads();

    if (h_f32) {
        #pragma unroll
        for (int i = 0; i < 2; i++) {
            int idx = i * 256 + tid;
            if (idx < 320) {
                int row = idx / 5, q = idx - row * 5;
                float4 v;
                v.x = s_h[row * 21 + q * 4 + 0];
                v.y = s_h[row * 21 + q * 4 + 1];
                v.z = s_h[row * 21 + q * 4 + 2];
                v.w = s_h[row * 21 + q * 4 + 3];
                *(float4*)(h_f32 + (size_t)(m0 + row) * LSTM + u0g + q * 4) = v;
            }
        }
    }
    if (h_h16) {
        // next-layer X: h lives at columns [3, 403)
        #pragma unroll
        for (int i = 0; i < 5; i++) {
            int idx = i * 256 + tid;             // [0,1280)
            int row = idx / 20, u = idx - row * 20;
            h_h16[(size_t)(m0 + row) * K23PADH + 3 + u0g + u] =
                __float2half_rn(s_h[row * 21 + u]);
        }
    }
}

// ---------------------------------------------------------------------------
// Attention: writes w as half straight into X2/X3 at column 403.
// ---------------------------------------------------------------------------
__global__ void attention_kernel(const float* __restrict__ w_prev,
                                 const float* __restrict__ inputs,
                                 const float* __restrict__ h1n,
                                 const float* __restrict__ kappa,
                                 const float* __restrict__ W_attn,
                                 const float* __restrict__ b_attn,
                                 const float* __restrict__ AV,
                                 const int* __restrict__ lens,
                                 __half* __restrict__ X2,
                                 __half* __restrict__ X3)
{
    int b = blockIdx.x;
    __shared__ float s_in[ATTN_IN];
    __shared__ float s_par[3 * NATTN];
    __shared__ float s_alpha[NATTN], s_beta[NATTN], s_kap[NATTN];
    __shared__ float s_phi[CHARLEN];
    int t = threadIdx.x;

    for (int i = t; i < 73; i += 128)  s_in[i]      = w_prev[b * 73 + i];
    if (t < 3)                          s_in[73 + t] = inputs[b * 3 + t];
    for (int i = t; i < 400; i += 128) s_in[76 + i] = h1n[b * LSTM + i];
    __syncthreads();

    {
        int out = t >> 2, ln = t & 3;
        float acc = 0.f;
        if (out < 30) {
            const float* wr = W_attn + out * ATTN_IN;
            for (int k = ln; k < ATTN_IN; k += 4) acc = fmaf(s_in[k], wr[k], acc);
        }
        acc += __shfl_down_sync(0xffffffffu, acc, 2);
        acc += __shfl_down_sync(0xffffffffu, acc, 1);
        if (ln == 0 && out < 30) {
            float x = acc + b_attn[out];
            s_par[out] = (x > 20.f) ? x : log1pf(expf(x));
        }
    }
    __syncthreads();

    if (t < NATTN) {
        s_alpha[t] = s_par[t];
        s_beta[t]  = fmaxf(s_par[NATTN + t], 0.01f);
        s_kap[t]   = kappa[b * NATTN + t] + s_par[2 * NATTN + t] * 0.04f;
    }
    __syncthreads();

    int len = lens[b];
    if (t < CHARLEN) {
        float u = (float)t;
        float phi = 0.f;
        #pragma unroll
        for (int i = 0; i < NATTN; i++) {
            float d = s_kap[i] - u;
            phi += s_alpha[i] * expf(-d * d / s_beta[i]);
        }
        s_phi[t] = (t < len) ? phi : 0.f;
    }
    __syncthreads();

    for (int v = t; v < VOCAB; v += 128) {
        float acc = 0.f;
        const float* av = AV + (size_t)b * (CHARLEN * VOCAB) + v;
        #pragma unroll 8
        for (int c = 0; c < CHARLEN; c++) acc = fmaf(s_phi[c], av[c * VOCAB], acc);
        __half hv = __float2half_rn(acc);
        X2[(size_t)b * K23PADH + 403 + v] = hv;
        X3[(size_t)b * K23PADH + 403 + v] = hv;
    }
}

// ---------------------------------------------------------------------------
// Launch
// ---------------------------------------------------------------------------
extern "C" void kernel_launch(void* const* d_in, const int* in_sizes, int n_in,
                              void* d_out, int out_size)
{
    const float* inputs = (const float*)d_in[0];
    const float* h1     = (const float*)d_in[1];
    const float* c1     = (const float*)d_in[2];
    const float* h2     = (const float*)d_in[3];
    const float* c2     = (const float*)d_in[4];
    const float* h3     = (const float*)d_in[5];
    const float* c3     = (const float*)d_in[6];
    const float* kappa  = (const float*)d_in[7];
    const float* w_prev = (const float*)d_in[8];
    const float* AV     = (const float*)d_in[9];
    const int*   lens   = (const int*)  d_in[10];
    const float* W_ih1  = (const float*)d_in[11];
    const float* W_hh1  = (const float*)d_in[12];
    const float* b1     = (const float*)d_in[13];
    const float* W_attn = (const float*)d_in[14];
    const float* b_attn = (const float*)d_in[15];
    const float* W_ih2  = (const float*)d_in[16];
    const float* W_hh2  = (const float*)d_in[17];
    const float* b2     = (const float*)d_in[18];
    const float* W_ih3  = (const float*)d_in[19];
    const float* W_hh3  = (const float*)d_in[20];
    const float* b3     = (const float*)d_in[21];
    float* out = (float*)d_out;

    __half *Wt1, *Wt2, *Wt3, *X1, *X2, *X3;
    float *h1n;
    cudaGetSymbolAddress((void**)&Wt1,  g_Wt1);
    cudaGetSymbolAddress((void**)&Wt2,  g_Wt2);
    cudaGetSymbolAddress((void**)&Wt3,  g_Wt3);
    cudaGetSymbolAddress((void**)&X1,   g_X1);
    cudaGetSymbolAddress((void**)&X2,   g_X2);
    cudaGetSymbolAddress((void**)&X3,   g_X3);
    cudaGetSymbolAddress((void**)&h1n,  g_h1n);

    cudaFuncSetAttribute(gemm_lstm, cudaFuncAttributeMaxDynamicSharedMemorySize, SMEM_GEMM);

    pack_w<<<(NGATE * K1PADH  + 255) / 256, 256>>>(W_ih1, W_hh1, Wt1, 76,  K1PADH);
    pack_w<<<(NGATE * K23PADH + 255) / 256, 256>>>(W_ih2, W_hh2, Wt2, 476, K23PADH);
    pack_w<<<(NGATE * K23PADH + 255) / 256, 256>>>(W_ih3, W_hh3, Wt3, 476, K23PADH);
    pack_x1<<<(BATCH * K1PADH + 255) / 256, 256>>>(w_prev, inputs, h1, X1);
    pack_static23<<<(BATCH * K23PADH + 255) / 256, 256>>>(inputs, h2, h3, X2, X3);

    dim3 ggrid(NGATE / NTILE, BATCH / MTILE);   // (20, 64)

    // LSTM 1: h1n fp32 (for attention) + half into X2 cols [3,403)
    gemm_lstm<<<ggrid, 256, SMEM_GEMM>>>(X1, Wt1, b1, c1, h1n, X2, K1PADH, K1PADH / 64);

    // Attention -> w half into X2/X3 cols [403,476)
    attention_kernel<<<BATCH, 128>>>(w_prev, inputs, h1n, kappa, W_attn, b_attn,
                                     AV, lens, X2, X3);

    // LSTM 2: half into X3 cols [3,403)
    gemm_lstm<<<ggrid, 256, SMEM_GEMM>>>(X2, Wt2, b2, c2, nullptr, X3, K23PADH, K23PADH / 64);

    // LSTM 3: fp32 to out
    gemm_lstm<<<ggrid, 256, SMEM_GEMM>>>(X3, Wt3, b3, c3, out, nullptr, K23PADH, K23PADH / 64);
}

// round 9
// speedup vs baseline: 4.8450x; 1.1036x over previous
#include <cuda_runtime.h>
#include <cuda_fp16.h>
#include <math.h>
#include <stdint.h>

// ---------------------------------------------------------------------------
// Problem constants
// ---------------------------------------------------------------------------
#define BATCH   4096
#define LSTM    400
#define VOCAB   73
#define NATTN   10
#define CHARLEN 64
#define NGATE   1600
#define K1PADH  512
#define K23PADH 896
#define ATTN_IN 476
#define NTILE   80
#define MTILE   64

// ---------------------------------------------------------------------------
// Scratch. X row-major half; Wt row-major [np][KPAD] half, np = unit*4+gate.
// X2/X3 cols: [0,3)=inputs, [3,403)=h(prev), [403,476)=w, [476,876)=hrec, rest 0.
// ---------------------------------------------------------------------------
__device__ __half g_Wt1[NGATE * K1PADH];
__device__ __half g_Wt2[NGATE * K23PADH];
__device__ __half g_Wt3[NGATE * K23PADH];
__device__ __half g_X1 [BATCH * K1PADH];
__device__ __half g_X2 [BATCH * K23PADH];
__device__ __half g_X3 [BATCH * K23PADH];
__device__ float  g_h1n[BATCH * LSTM];

#define CPASYNC16(dst, src) \
    asm volatile("cp.async.cg.shared.global [%0], [%1], 16;" :: "r"(dst), "l"(src) : "memory")

__device__ __forceinline__ uint32_t smem_to_u32(const void* p) {
    uint32_t a;
    asm("{ .reg .u64 t; cvta.to.shared.u64 t, %1; cvt.u32.u64 %0, t; }" : "=r"(a) : "l"(p));
    return a;
}

__device__ __forceinline__ void mma_f16(float* d, const uint32_t* a, const uint32_t* b) {
    asm volatile(
        "mma.sync.aligned.m16n8k16.row.col.f32.f16.f16.f32 "
        "{%0,%1,%2,%3}, {%4,%5,%6,%7}, {%8,%9}, {%0,%1,%2,%3};"
        : "+f"(d[0]), "+f"(d[1]), "+f"(d[2]), "+f"(d[3])
        : "r"(a[0]), "r"(a[1]), "r"(a[2]), "r"(a[3]), "r"(b[0]), "r"(b[1]));
}

__device__ __forceinline__ void ldsm_x4(uint32_t& r0, uint32_t& r1, uint32_t& r2,
                                        uint32_t& r3, uint32_t addr) {
    asm volatile("ldmatrix.sync.aligned.m8n8.x4.shared.b16 {%0,%1,%2,%3}, [%4];"
                 : "=r"(r0), "=r"(r1), "=r"(r2), "=r"(r3) : "r"(addr));
}
__device__ __forceinline__ void ldsm_x2(uint32_t& r0, uint32_t& r1, uint32_t addr) {
    asm volatile("ldmatrix.sync.aligned.m8n8.x2.shared.b16 {%0,%1}, [%2];"
                 : "=r"(r0), "=r"(r1) : "r"(addr));
}

// ---------------------------------------------------------------------------
// ONE merged pack kernel: W1 | W2 | W3 | X1 | X23-static (compacted columns)
// ---------------------------------------------------------------------------
#define R_W1  (NGATE * K1PADH)                 // 819200
#define R_W2  (R_W1 + NGATE * K23PADH)         // 2252800
#define R_W3  (R_W2 + NGATE * K23PADH)         // 3686400
#define R_X1  (R_W3 + BATCH * K1PADH)          // 5783552
#define XSCOL 423                              // 3 inputs + 400 hrec + 20 pad
#define R_XS  (R_X1 + BATCH * XSCOL)           // 7516004... computed below
#define PACK_TOTAL (R_X1 + BATCH * XSCOL)

__global__ void pack_all(const float* __restrict__ W_ih1, const float* __restrict__ W_hh1,
                         const float* __restrict__ W_ih2, const float* __restrict__ W_hh2,
                         const float* __restrict__ W_ih3, const float* __restrict__ W_hh3,
                         const float* __restrict__ w_prev, const float* __restrict__ inputs,
                         const float* __restrict__ h1, const float* __restrict__ h2,
                         const float* __restrict__ h3,
                         __half* __restrict__ Wt1, __half* __restrict__ Wt2,
                         __half* __restrict__ Wt3, __half* __restrict__ X1,
                         __half* __restrict__ X2, __half* __restrict__ X3)
{
    int idx = blockIdx.x * blockDim.x + threadIdx.x;
    if (idx >= PACK_TOTAL) return;
    if (idx < R_W1) {
        int np = idx / K1PADH, k = idx - np * K1PADH;
        int n = (np & 3) * LSTM + (np >> 2);
        float v = 0.f;
        if (k < 76)            v = W_ih1[n * 76 + k];
        else if (k < 476)      v = W_hh1[n * LSTM + (k - 76)];
        Wt1[idx] = __float2half_rn(v);
    } else if (idx < R_W2) {
        int r = idx - R_W1;
        int np = r / K23PADH, k = r - np * K23PADH;
        int n = (np & 3) * LSTM + (np >> 2);
        float v = 0.f;
        if (k < 476)           v = W_ih2[n * 476 + k];
        else if (k < 876)      v = W_hh2[n * LSTM + (k - 476)];
        Wt2[r] = __float2half_rn(v);
    } else if (idx < R_W3) {
        int r = idx - R_W2;
        int np = r / K23PADH, k = r - np * K23PADH;
        int n = (np & 3) * LSTM + (np >> 2);
        float v = 0.f;
        if (k < 476)           v = W_ih3[n * 476 + k];
        else if (k < 876)      v = W_hh3[n * LSTM + (k - 476)];
        Wt3[r] = __float2half_rn(v);
    } else if (idx < R_X1) {
        int r = idx - R_W3;
        int b = r >> 9, c = r & 511;
        float v;
        if      (c < 73)  v = w_prev[b * 73 + c];
        else if (c < 76)  v = inputs[b * 3 + (c - 73)];
        else if (c < 476) v = h1[b * LSTM + (c - 76)];
        else              v = 0.f;
        X1[r] = __float2half_rn(v);
    } else {
        int r = idx - R_X1;
        int b = r / XSCOL, cp = r - b * XSCOL;
        int c = (cp < 3) ? cp : (cp + 473);     // maps to {0,1,2} U [476,896)
        __half v2, v3;
        if (c < 3) {
            __half v = __float2half_rn(inputs[b * 3 + c]);
            v2 = v; v3 = v;
        } else if (c < 876) {
            v2 = __float2half_rn(h2[b * LSTM + (c - 476)]);
            v3 = __float2half_rn(h3[b * LSTM + (c - 476)]);
        } else {
            v2 = __float2half_rn(0.f); v3 = v2;
        }
        size_t o = (size_t)b * K23PADH + c;
        X2[o] = v2; X3[o] = v3;
    }
}

// ---------------------------------------------------------------------------
// Fused fp16 mma.sync GEMM + LSTM epilogue.
// CTA 64(M) x 80(N), 4 warps (2M x 2N), warp tile 32x40, BK=64.
// 2-stage cp.async pipeline, 5 CTAs/SM. Crossbar per chunk: 36KB (vs 57KB r8).
// ---------------------------------------------------------------------------
#define SMSTRH   72
#define A_BYTES  (MTILE * SMSTRH * 2)        // 9216
#define B_BYTES  (NTILE * SMSTRH * 2)        // 11520
#define STAGE_BYTES (A_BYTES + B_BYTES)      // 20736
#define NSTAGE   2
#define SMEM_GEMM (NSTAGE * STAGE_BYTES)     // 41472

__global__ __launch_bounds__(128, 5)
void gemm_lstm(const __half* __restrict__ A, const __half* __restrict__ Bw,
               const float* __restrict__ bias, const float* __restrict__ c_in,
               float* __restrict__ h_f32, __half* __restrict__ h_h16,
               int KPAD, int NC)
{
    extern __shared__ char smem[];
    float* smemf = (float*)smem;
    const uint32_t sb = smem_to_u32(smem);
    const int tid = threadIdx.x, wid = tid >> 5, lane = tid & 31;
    const int warp_m = wid & 1, warp_n = wid >> 1;
    const int n0 = blockIdx.x * NTILE;
    const int m0 = blockIdx.y * MTILE;

    const __half* Ag = A  + (size_t)m0 * KPAD;
    const __half* Bg = Bw + (size_t)n0 * KPAD;

    float acc[2][5][4];
    #pragma unroll
    for (int mt = 0; mt < 2; mt++)
        #pragma unroll
        for (int nt = 0; nt < 5; nt++)
            #pragma unroll
            for (int q = 0; q < 4; q++) acc[mt][nt][q] = 0.f;

    // ---- ldmatrix per-thread offsets (relative to stage base) ----
    const int lane8 = lane & 7, mat = lane >> 3;
    uint32_t aoff[2], boff[2], boff2;
    #pragma unroll
    for (int mt = 0; mt < 2; mt++) {
        int arow = warp_m * 32 + mt * 16 + (mat & 1) * 8 + lane8;
        aoff[mt] = (uint32_t)((arow * SMSTRH + (mat >> 1) * 8) * 2);
    }
    #pragma unroll
    for (int p = 0; p < 2; p++) {
        int brow = warp_n * 40 + p * 16 + (mat >> 1) * 8 + lane8;
        boff[p] = (uint32_t)(A_BYTES + (brow * SMSTRH + (mat & 1) * 8) * 2);
    }
    {
        int m2 = (lane >> 3) & 1;
        int brow = warp_n * 40 + 32 + lane8;
        boff2 = (uint32_t)(A_BYTES + (brow * SMSTRH + m2 * 8) * 2);
    }

    // per chunk: A 512 x 16B ops; B 640 x 16B ops (128 threads)
    auto issue_chunk = [&](int c, int stage) {
        uint32_t abase = sb + stage * STAGE_BYTES;
        uint32_t bbase = abase + A_BYTES;
        int k0 = c * 64;
        #pragma unroll
        for (int i = 0; i < 4; i++) {
            int o = i * 128 + tid;          // [0,512)
            int row = o >> 3, seg = o & 7;
            CPASYNC16(abase + row * (SMSTRH * 2) + seg * 16,
                      Ag + (size_t)row * KPAD + k0 + seg * 8);
        }
        #pragma unroll
        for (int i = 0; i < 5; i++) {
            int o = i * 128 + tid;          // [0,640)
            int row = o >> 3, seg = o & 7;
            CPASYNC16(bbase + row * (SMSTRH * 2) + seg * 16,
                      Bg + (size_t)row * KPAD + k0 + seg * 8);
        }
        asm volatile("cp.async.commit_group;" ::: "memory");
    };

    issue_chunk(0, 0);

    #pragma unroll 1
    for (int c = 0; c < NC; ++c) {
        asm volatile("cp.async.wait_group 0;" ::: "memory");
        __syncthreads();   // chunk c visible; compute of c-1 done before overwrite
        if (c + 1 < NC) issue_chunk(c + 1, (c + 1) & 1);

        const uint32_t sbase = sb + (c & 1) * STAGE_BYTES;
        #pragma unroll
        for (int ks = 0; ks < 4; ks++) {
            uint32_t koff = sbase + ks * 32;
            uint32_t a[2][4], b[5][2];
            ldsm_x4(a[0][0], a[0][1], a[0][2], a[0][3], koff + aoff[0]);
            ldsm_x4(a[1][0], a[1][1], a[1][2], a[1][3], koff + aoff[1]);
            ldsm_x4(b[0][0], b[0][1], b[1][0], b[1][1], koff + boff[0]);
            ldsm_x4(b[2][0], b[2][1], b[3][0], b[3][1], koff + boff[1]);
            ldsm_x2(b[4][0], b[4][1], koff + boff2);
            #pragma unroll
            for (int mt = 0; mt < 2; mt++)
                #pragma unroll
                for (int nt = 0; nt < 5; nt++)
                    mma_f16(acc[mt][nt], a[mt], b[nt]);
        }
    }
    __syncthreads();

    // ---- epilogue: bias + LSTM cell ----
    float* s_c    = smemf;                   // [64][21]
    float* s_h    = smemf + 64 * 21;         // [64][21]
    float* s_bias = smemf + 2 * 64 * 21;     // [80]

    const int u0g = blockIdx.x * 20;
    if (tid < NTILE) {
        int jg = n0 + tid;
        s_bias[tid] = bias[(jg & 3) * LSTM + (jg >> 2)];
    }
    #pragma unroll
    for (int i = 0; i < 3; i++) {
        int idx = i * 128 + tid;             // [0,320)
        if (idx < 320) {
            int row = idx / 5, q = idx - row * 5;
            float4 v = *(const float4*)(c_in + (size_t)(m0 + row) * LSTM + u0g + q * 4);
            s_c[row * 21 + q * 4 + 0] = v.x;
            s_c[row * 21 + q * 4 + 1] = v.y;
            s_c[row * 21 + q * 4 + 2] = v.z;
            s_c[row * 21 + q * 4 + 3] = v.w;
        }
    }
    __syncthreads();

    const int gid = lane >> 2, tig = lane & 3;
    #pragma unroll
    for (int mt = 0; mt < 2; mt++) {
        #pragma unroll
        for (int nt = 0; nt < 5; nt++) {
            float p0 = __shfl_xor_sync(0xffffffffu, acc[mt][nt][0], 1);
            float p1 = __shfl_xor_sync(0xffffffffu, acc[mt][nt][1], 1);
            float p2 = __shfl_xor_sync(0xffffffffu, acc[mt][nt][2], 1);
            float p3 = __shfl_xor_sync(0xffffffffu, acc[mt][nt][3], 1);
            if (!(lane & 1)) {
                int jb = warp_n * 40 + nt * 8 + tig * 2;
                int u  = jb >> 2;
                float bi = s_bias[jb], bf = s_bias[jb + 1];
                float bg = s_bias[jb + 2], bo = s_bias[jb + 3];
                int r0 = warp_m * 32 + mt * 16 + gid;
                #pragma unroll
                for (int hh = 0; hh < 2; hh++) {
                    int r = r0 + hh * 8;
                    float vi = (hh ? acc[mt][nt][2] : acc[mt][nt][0]) + bi;
                    float vf = (hh ? acc[mt][nt][3] : acc[mt][nt][1]) + bf;
                    float vg = (hh ? p2 : p0) + bg;
                    float vo = (hh ? p3 : p1) + bo;
                    float ii = 1.f / (1.f + expf(-vi));
                    float ff = 1.f / (1.f + expf(-vf));
                    float oo = 1.f / (1.f + expf(-vo));
                    float gg = tanhf(vg);
                    float cc = ff * s_c[r * 21 + u] + ii * gg;
                    s_h[r * 21 + u] = oo * tanhf(cc);
                }
            }
        }
    }
    __syncthreads();

    if (h_f32) {
        #pragma unroll
        for (int i = 0; i < 3; i++) {
            int idx = i * 128 + tid;
            if (idx < 320) {
                int row = idx / 5, q = idx - row * 5;
                float4 v;
                v.x = s_h[row * 21 + q * 4 + 0];
                v.y = s_h[row * 21 + q * 4 + 1];
                v.z = s_h[row * 21 + q * 4 + 2];
                v.w = s_h[row * 21 + q * 4 + 3];
                *(float4*)(h_f32 + (size_t)(m0 + row) * LSTM + u0g + q * 4) = v;
            }
        }
    }
    if (h_h16) {
        #pragma unroll
        for (int i = 0; i < 10; i++) {
            int idx = i * 128 + tid;             // [0,1280)
            int row = idx / 20, u = idx - row * 20;
            h_h16[(size_t)(m0 + row) * K23PADH + 3 + u0g + u] =
                __float2half_rn(s_h[row * 21 + u]);
        }
    }
}

// ---------------------------------------------------------------------------
// Attention: writes w as half straight into X2/X3 at column 403.
// ---------------------------------------------------------------------------
__global__ void attention_kernel(const float* __restrict__ w_prev,
                                 const float* __restrict__ inputs,
                                 const float* __restrict__ h1n,
                                 const float* __restrict__ kappa,
                                 const float* __restrict__ W_attn,
                                 const float* __restrict__ b_attn,
                                 const float* __restrict__ AV,
                                 const int* __restrict__ lens,
                                 __half* __restrict__ X2,
                                 __half* __restrict__ X3)
{
    int b = blockIdx.x;
    __shared__ float s_in[ATTN_IN];
    __shared__ float s_par[3 * NATTN];
    __shared__ float s_alpha[NATTN], s_beta[NATTN], s_kap[NATTN];
    __shared__ float s_phi[CHARLEN];
    int t = threadIdx.x;

    for (int i = t; i < 73; i += 128)  s_in[i]      = w_prev[b * 73 + i];
    if (t < 3)                          s_in[73 + t] = inputs[b * 3 + t];
    for (int i = t; i < 400; i += 128) s_in[76 + i] = h1n[b * LSTM + i];
    __syncthreads();

    {
        int out = t >> 2, ln = t & 3;
        float acc = 0.f;
        if (out < 30) {
            const float* wr = W_attn + out * ATTN_IN;
            for (int k = ln; k < ATTN_IN; k += 4) acc = fmaf(s_in[k], wr[k], acc);
        }
        acc += __shfl_down_sync(0xffffffffu, acc, 2);
        acc += __shfl_down_sync(0xffffffffu, acc, 1);
        if (ln == 0 && out < 30) {
            float x = acc + b_attn[out];
            s_par[out] = (x > 20.f) ? x : log1pf(expf(x));
        }
    }
    __syncthreads();

    if (t < NATTN) {
        s_alpha[t] = s_par[t];
        s_beta[t]  = fmaxf(s_par[NATTN + t], 0.01f);
        s_kap[t]   = kappa[b * NATTN + t] + s_par[2 * NATTN + t] * 0.04f;
    }
    __syncthreads();

    int len = lens[b];
    if (t < CHARLEN) {
        float u = (float)t;
        float phi = 0.f;
        #pragma unroll
        for (int i = 0; i < NATTN; i++) {
            float d = s_kap[i] - u;
            phi += s_alpha[i] * expf(-d * d / s_beta[i]);
        }
        s_phi[t] = (t < len) ? phi : 0.f;
    }
    __syncthreads();

    for (int v = t; v < VOCAB; v += 128) {
        float acc = 0.f;
        const float* av = AV + (size_t)b * (CHARLEN * VOCAB) + v;
        #pragma unroll 8
        for (int c = 0; c < CHARLEN; c++) acc = fmaf(s_phi[c], av[c * VOCAB], acc);
        __half hv = __float2half_rn(acc);
        X2[(size_t)b * K23PADH + 403 + v] = hv;
        X3[(size_t)b * K23PADH + 403 + v] = hv;
    }
}

// ---------------------------------------------------------------------------
// Launch
// ---------------------------------------------------------------------------
extern "C" void kernel_launch(void* const* d_in, const int* in_sizes, int n_in,
                              void* d_out, int out_size)
{
    const float* inputs = (const float*)d_in[0];
    const float* h1     = (const float*)d_in[1];
    const float* c1     = (const float*)d_in[2];
    const float* h2     = (const float*)d_in[3];
    const float* c2     = (const float*)d_in[4];
    const float* h3     = (const float*)d_in[5];
    const float* c3     = (const float*)d_in[6];
    const float* kappa  = (const float*)d_in[7];
    const float* w_prev = (const float*)d_in[8];
    const float* AV     = (const float*)d_in[9];
    const int*   lens   = (const int*)  d_in[10];
    const float* W_ih1  = (const float*)d_in[11];
    const float* W_hh1  = (const float*)d_in[12];
    const float* b1     = (const float*)d_in[13];
    const float* W_attn = (const float*)d_in[14];
    const float* b_attn = (const float*)d_in[15];
    const float* W_ih2  = (const float*)d_in[16];
    const float* W_hh2  = (const float*)d_in[17];
    const float* b2     = (const float*)d_in[18];
    const float* W_ih3  = (const float*)d_in[19];
    const float* W_hh3  = (const float*)d_in[20];
    const float* b3     = (const float*)d_in[21];
    float* out = (float*)d_out;

    __half *Wt1, *Wt2, *Wt3, *X1, *X2, *X3;
    float *h1n;
    cudaGetSymbolAddress((void**)&Wt1,  g_Wt1);
    cudaGetSymbolAddress((void**)&Wt2,  g_Wt2);
    cudaGetSymbolAddress((void**)&Wt3,  g_Wt3);
    cudaGetSymbolAddress((void**)&X1,   g_X1);
    cudaGetSymbolAddress((void**)&X2,   g_X2);
    cudaGetSymbolAddress((void**)&X3,   g_X3);
    cudaGetSymbolAddress((void**)&h1n,  g_h1n);

    cudaFuncSetAttribute(gemm_lstm, cudaFuncAttributeMaxDynamicSharedMemorySize, SMEM_GEMM);

    pack_all<<<(PACK_TOTAL + 255) / 256, 256>>>(W_ih1, W_hh1, W_ih2, W_hh2, W_ih3, W_hh3,
                                                w_prev, inputs, h1, h2, h3,
                                                Wt1, Wt2, Wt3, X1, X2, X3);

    dim3 ggrid(NGATE / NTILE, BATCH / MTILE);   // (20, 64)

    // LSTM 1: h1n fp32 (for attention) + half into X2 cols [3,403)
    gemm_lstm<<<ggrid, 128, SMEM_GEMM>>>(X1, Wt1, b1, c1, h1n, X2, K1PADH, K1PADH / 64);

    // Attention -> w half into X2/X3 cols [403,476)
    attention_kernel<<<BATCH, 128>>>(w_prev, inputs, h1n, kappa, W_attn, b_attn,
                                     AV, lens, X2, X3);

    // LSTM 2: half into X3 cols [3,403)
    gemm_lstm<<<ggrid, 128, SMEM_GEMM>>>(X2, Wt2, b2, c2, nullptr, X3, K23PADH, K23PADH / 64);

    // LSTM 3: fp32 to out
    gemm_lstm<<<ggrid, 128, SMEM_GEMM>>>(X3, Wt3, b3, c3, out, nullptr, K23PADH, K23PADH / 64);
}